// round 7
// baseline (speedup 1.0000x reference)
#include <cuda_runtime.h>
#include <cuda_fp16.h>
#include <cstdint>

#define NB      256
#define KS      64
#define DMODEL  1024
#define NQKV    3072
#define NH      16
#define DHEAD   64
#define NROWS   (NB*KS)          // 16384
#define SCALE   0.125f
#define LNEPS   1e-5f

#define SMEM_SWIZZLE_128B(o) ((o) ^ (((o) >> 3) & 0x70))

__device__ __forceinline__ uint32_t smem_to_u32(const void* p) {
    uint32_t a;
    asm("{ .reg .u64 t; cvta.to.shared.u64 t, %1; cvt.u32.u64 %0, t; }" : "=r"(a) : "l"(p));
    return a;
}
__device__ __forceinline__ void ldsm4(uint32_t* r, uint32_t addr) {
    asm volatile("ldmatrix.sync.aligned.m8n8.x4.shared.b16 {%0,%1,%2,%3}, [%4];"
        : "=r"(r[0]), "=r"(r[1]), "=r"(r[2]), "=r"(r[3]) : "r"(addr));
}
__device__ __forceinline__ void ldsm4t(uint32_t* r, uint32_t addr) {
    asm volatile("ldmatrix.sync.aligned.m8n8.x4.trans.shared.b16 {%0,%1,%2,%3}, [%4];"
        : "=r"(r[0]), "=r"(r[1]), "=r"(r[2]), "=r"(r[3]) : "r"(addr));
}
__device__ __forceinline__ void mma_fp16(float* c, const uint32_t* a, const uint32_t* b) {
    asm volatile("mma.sync.aligned.m16n8k16.row.col.f32.f16.f16.f32 "
        "{%0,%1,%2,%3}, {%4,%5,%6,%7}, {%8,%9}, {%0,%1,%2,%3};"
        : "+f"(c[0]), "+f"(c[1]), "+f"(c[2]), "+f"(c[3])
        : "r"(a[0]), "r"(a[1]), "r"(a[2]), "r"(a[3]), "r"(b[0]), "r"(b[1]));
}
#define CP_ASYNC16(dst, src) \
    asm volatile("cp.async.cg.shared.global [%0], [%1], 16;" :: "r"(dst), "l"(src))
#define CP_COMMIT() asm volatile("cp.async.commit_group;" ::: "memory")
#define CP_WAIT(n)  asm volatile("cp.async.wait_group %0;" :: "n"(n) : "memory")

// ===================== scratch =====================
__device__ float  g_mask[NROWS];
__device__ int    g_masktype;
__device__ __half g_hh[NROWS*DMODEL];      // hidden fp16
__device__ __half g_qkvh[NROWS*NQKV];      // fused QKV output, row stride 3072
__device__ __half g_aoh[NROWS*DMODEL];     // attention out fp16
__device__ __half g_projh[NROWS*DMODEL];   // W_o projection fp16
__device__ __half g_wh[4*DMODEL*DMODEL];   // weights fp16 (Wq|Wk|Wv|Wo)

// ===================== mask handling =====================
__global__ void detect_mask(const unsigned char* __restrict__ p) {
    __shared__ int sflt, smis;
    if (threadIdx.x == 0) { sflt = 0; smis = 0; }
    __syncthreads();
    int f = 0, ms = 0;
    for (int i = threadIdx.x; i < NROWS; i += 256) {
        unsigned char v = p[i];
        if (v > 1) f = 1;
        if (v != 0 && (i & 3)) ms = 1;
    }
    if (f)  atomicOr(&sflt, 1);
    if (ms) atomicOr(&smis, 1);
    __syncthreads();
    if (threadIdx.x == 0) g_masktype = sflt ? 0 : (smis ? 1 : 2);
}

__global__ void norm_mask(const void* __restrict__ p) {
    int i = blockIdx.x * blockDim.x + threadIdx.x;
    if (i >= NROWS) return;
    int t = g_masktype;
    float m;
    if (t == 0)      m = (((const float*)p)[i] != 0.0f) ? 1.0f : 0.0f;
    else if (t == 1) m = (((const unsigned char*)p)[i] != 0) ? 1.0f : 0.0f;
    else             m = (((const int*)p)[i] != 0) ? 1.0f : 0.0f;
    g_mask[i] = m;
}

// ===================== merged fp32 -> fp16 convert (hidden + 4 weights) ======
// blocks [0, 16384): hidden (4.19M float4). blocks [16384, 20480): weights.
__global__ __launch_bounds__(256) void conv_all(
    const float4* __restrict__ hidden,
    const float4* __restrict__ w0, const float4* __restrict__ w1,
    const float4* __restrict__ w2, const float4* __restrict__ w3,
    uint2* __restrict__ dh, uint2* __restrict__ dw)
{
    const int bid = blockIdx.x;
    const float4* src;
    uint2* dst;
    int i;
    if (bid < 16384) {
        i = bid * 256 + threadIdx.x;
        src = hidden; dst = dh;
    } else {
        const int t = bid - 16384;
        const int w = t >> 10;
        src = (w == 0) ? w0 : (w == 1) ? w1 : (w == 2) ? w2 : w3;
        dst = dw + (size_t)w * (DMODEL * DMODEL / 4);
        i = (t & 1023) * 256 + threadIdx.x;
    }
    float4 v = src[i];
    __half2 a = __floats2half2_rn(v.x, v.y);
    __half2 b = __floats2half2_rn(v.z, v.w);
    uint2 u;
    u.x = *(uint32_t*)&a; u.y = *(uint32_t*)&b;
    dst[i] = u;
}

// ===================== fp16 HMMA GEMM: C = A @ B^T, fp16 out ================
// CTA tile 128x256, warp tile 64x64 (8 warps, 2x4), K-tile 64, 4-stage,
// 1 CTA/SM (192KB smem).
#define STAGE_BYTES 49152        // A 16K | B 32K
#define GSTAGES 4
#define GEMM_SMEM (GSTAGES * STAGE_BYTES)
#define NKT 16

__device__ __forceinline__ void load_stage_async(
    uint32_t sbase,
    const __half* __restrict__ A, const __half* __restrict__ B,
    int m0, int n0, int k0, int tid)
{
#pragma unroll
    for (int i = 0; i < 12; i++) {
        const int idx = tid + i * 256;           // 0..3071 16B chunks
        if (idx < 1024) {                        // A: 128 rows x 8 chunks
            const int r = idx >> 3, cc = idx & 7;
            uint32_t so = sbase + SMEM_SWIZZLE_128B((uint32_t)(r * 128 + cc * 16));
            CP_ASYNC16(so, A + (size_t)(m0 + r) * DMODEL + k0 + cc * 8);
        } else {                                 // B: 256 rows x 8 chunks
            const int j = idx - 1024;
            const int r = j >> 3, cc = j & 7;
            uint32_t so = sbase + 16384 + SMEM_SWIZZLE_128B((uint32_t)(r * 128 + cc * 16));
            CP_ASYNC16(so, B + (size_t)(n0 + r) * DMODEL + k0 + cc * 8);
        }
    }
}

__global__ __launch_bounds__(256, 1) void gemm_fp16(
    const __half* __restrict__ A, const __half* __restrict__ B,
    __half* __restrict__ C, int ldC)
{
    extern __shared__ char sm[];
    const uint32_t smem_base = smem_to_u32(sm);
    const int tid  = threadIdx.x;
    const int lane = tid & 31;
    const int wid  = tid >> 5;
    const int warp_m = wid & 1;      // 2 warps in M
    const int warp_n = wid >> 1;     // 4 warps in N
    const int m0 = blockIdx.y * 128;
    const int n0 = blockIdx.x * 256;
    const int m0w = warp_m * 64, n0w = warp_n * 64;

    float c[4][8][4];
#pragma unroll
    for (int mi = 0; mi < 4; mi++)
#pragma unroll
        for (int ni = 0; ni < 8; ni++)
#pragma unroll
            for (int e = 0; e < 4; e++) c[mi][ni][e] = 0.0f;

    load_stage_async(smem_base + 0 * STAGE_BYTES, A, B, m0, n0, 0, tid);
    CP_COMMIT();
    load_stage_async(smem_base + 1 * STAGE_BYTES, A, B, m0, n0, 64, tid);
    CP_COMMIT();
    load_stage_async(smem_base + 2 * STAGE_BYTES, A, B, m0, n0, 128, tid);
    CP_COMMIT();

    const int arow  = m0w + (lane & 15);
    const int abyt  = ((lane >> 4) & 1) * 16;
    const int brow  = ((lane >> 4) & 1) * 8 + (lane & 7);
    const int bbyt  = ((lane >> 3) & 1) * 16;

    for (int kt = 0; kt < NKT; kt++) {
        CP_WAIT(2);
        __syncthreads();
        if (kt + 3 < NKT) {
            load_stage_async(smem_base + ((kt + 3) & 3) * STAGE_BYTES, A, B,
                             m0, n0, (kt + 3) * 64, tid);
        }
        CP_COMMIT();

        const uint32_t sb = smem_base + (kt & 3) * STAGE_BYTES;
#pragma unroll
        for (int ks = 0; ks < 4; ks++) {
            uint32_t af[4][4];
#pragma unroll
            for (int mi = 0; mi < 4; mi++) {
                uint32_t off = SMEM_SWIZZLE_128B((uint32_t)((arow + mi * 16) * 128 + ks * 32 + abyt));
                ldsm4(af[mi], sb + off);
            }
            uint32_t bf[4][4];
#pragma unroll
            for (int p = 0; p < 4; p++) {
                uint32_t off = SMEM_SWIZZLE_128B((uint32_t)((n0w + p * 16 + brow) * 128 + ks * 32 + bbyt));
                ldsm4(bf[p], sb + 16384 + off);
            }
#pragma unroll
            for (int mi = 0; mi < 4; mi++)
#pragma unroll
                for (int ni = 0; ni < 8; ni++)
                    mma_fp16(c[mi][ni], af[mi], &bf[ni >> 1][(ni & 1) * 2]);
        }
    }

#pragma unroll
    for (int mi = 0; mi < 4; mi++) {
        const int r0 = m0 + m0w + mi * 16 + (lane >> 2);
#pragma unroll
        for (int ni = 0; ni < 8; ni++) {
            const int cc = n0 + n0w + ni * 8 + (lane & 3) * 2;
            __half2 p0 = __floats2half2_rn(c[mi][ni][0], c[mi][ni][1]);
            __half2 p1 = __floats2half2_rn(c[mi][ni][2], c[mi][ni][3]);
            *(__half2*)(C + (size_t)r0 * ldC + cc)       = p0;
            *(__half2*)(C + (size_t)(r0 + 8) * ldC + cc) = p1;
        }
    }
}

// ===================== HMMA attention: one CTA (128 thr) per (b,h) ==========
__global__ __launch_bounds__(128) void attn_hmma() {
    __shared__ __half sQ[64 * 64];
    __shared__ __half sK[64 * 64];
    __shared__ __half sV[64 * 64];
    __shared__ __half sS[64 * 64];

    const int bh   = blockIdx.x;
    const int b    = bh >> 4;
    const int h    = bh & 15;
    const int tid  = threadIdx.x;
    const int lane = tid & 31;
    const int wid  = tid >> 5;

    const uint32_t q_s = smem_to_u32(sQ);
    const uint32_t k_s = smem_to_u32(sK);
    const uint32_t v_s = smem_to_u32(sV);
    const uint32_t s_s = smem_to_u32(sS);

    // QKV rows have stride NQKV; Q at col h*64, K at 1024+h*64, V at 2048+h*64
    const size_t qbase = (size_t)(b * KS) * NQKV + h * DHEAD;

#pragma unroll
    for (int i = 0; i < 4; i++) {
        int idx = tid + i * 128;
        int r = idx >> 3, ch = idx & 7;
        size_t ga = qbase + (size_t)r * NQKV + ch * 8;
        uint32_t so = SMEM_SWIZZLE_128B((uint32_t)(r * 128 + ch * 16));
        *(uint4*)((char*)sQ + so) = *(const uint4*)&g_qkvh[ga];
        *(uint4*)((char*)sK + so) = *(const uint4*)&g_qkvh[ga + 1024];
        *(uint4*)((char*)sV + so) = *(const uint4*)&g_qkvh[ga + 2048];
    }
    __syncthreads();

    float c[8][4];
#pragma unroll
    for (int nb = 0; nb < 8; nb++)
#pragma unroll
        for (int e = 0; e < 4; e++) c[nb][e] = 0.0f;

    const int arow = wid * 16 + (lane & 15);
    const int abyt = ((lane >> 4) & 1) * 16;
    const int brow = ((lane >> 4) & 1) * 8 + (lane & 7);
    const int bbyt = ((lane >> 3) & 1) * 16;

#pragma unroll
    for (int ks = 0; ks < 4; ks++) {
        uint32_t af[4];
        ldsm4(af, q_s + SMEM_SWIZZLE_128B((uint32_t)(arow * 128 + ks * 32 + abyt)));
        uint32_t bf[4][4];
#pragma unroll
        for (int p = 0; p < 4; p++)
            ldsm4(bf[p], k_s + SMEM_SWIZZLE_128B((uint32_t)((p * 16 + brow) * 128 + ks * 32 + bbyt)));
#pragma unroll
        for (int nb = 0; nb < 8; nb++)
            mma_fp16(c[nb], af, &bf[nb >> 1][(nb & 1) * 2]);
    }

    const int r0 = wid * 16 + (lane >> 2);
    const int r1 = r0 + 8;
    float m0 = -1e30f, m1 = -1e30f;
#pragma unroll
    for (int nb = 0; nb < 8; nb++) {
#pragma unroll
        for (int e = 0; e < 4; e++) c[nb][e] *= SCALE;
        m0 = fmaxf(m0, fmaxf(c[nb][0], c[nb][1]));
        m1 = fmaxf(m1, fmaxf(c[nb][2], c[nb][3]));
    }
    m0 = fmaxf(m0, __shfl_xor_sync(0xffffffffu, m0, 1));
    m0 = fmaxf(m0, __shfl_xor_sync(0xffffffffu, m0, 2));
    m1 = fmaxf(m1, __shfl_xor_sync(0xffffffffu, m1, 1));
    m1 = fmaxf(m1, __shfl_xor_sync(0xffffffffu, m1, 2));
    float s0 = 0.0f, s1 = 0.0f;
#pragma unroll
    for (int nb = 0; nb < 8; nb++) {
        c[nb][0] = __expf(c[nb][0] - m0); s0 += c[nb][0];
        c[nb][1] = __expf(c[nb][1] - m0); s0 += c[nb][1];
        c[nb][2] = __expf(c[nb][2] - m1); s1 += c[nb][2];
        c[nb][3] = __expf(c[nb][3] - m1); s1 += c[nb][3];
    }
    s0 += __shfl_xor_sync(0xffffffffu, s0, 1);
    s0 += __shfl_xor_sync(0xffffffffu, s0, 2);
    s1 += __shfl_xor_sync(0xffffffffu, s1, 1);
    s1 += __shfl_xor_sync(0xffffffffu, s1, 2);
    const float w0 = g_mask[b * KS + r0] / s0;
    const float w1 = g_mask[b * KS + r1] / s1;

    const int scol = (lane & 3) * 2;
#pragma unroll
    for (int nb = 0; nb < 8; nb++) {
        __half2 p0 = __floats2half2_rn(c[nb][0] * w0, c[nb][1] * w0);
        __half2 p1 = __floats2half2_rn(c[nb][2] * w1, c[nb][3] * w1);
        *(__half2*)((char*)sS + SMEM_SWIZZLE_128B((uint32_t)(r0 * 128 + (nb * 8 + scol) * 2))) = p0;
        *(__half2*)((char*)sS + SMEM_SWIZZLE_128B((uint32_t)(r1 * 128 + (nb * 8 + scol) * 2))) = p1;
    }
    __syncwarp();

    float o[8][4];
#pragma unroll
    for (int nb = 0; nb < 8; nb++)
#pragma unroll
        for (int e = 0; e < 4; e++) o[nb][e] = 0.0f;

    const int g  = lane >> 3;
    const int gr = lane & 7;
#pragma unroll
    for (int ks = 0; ks < 4; ks++) {
        uint32_t af[4];
        ldsm4(af, s_s + SMEM_SWIZZLE_128B((uint32_t)(arow * 128 + ks * 32 + abyt)));
#pragma unroll
        for (int np = 0; np < 4; np++) {
            uint32_t bf[4];
            const int krow = ks * 16 + (g & 1) * 8 + gr;
            const int dcol = np * 16 + (g >> 1) * 8;
            ldsm4t(bf, v_s + SMEM_SWIZZLE_128B((uint32_t)(krow * 128 + dcol * 2)));
            mma_fp16(o[np * 2 + 0], af, &bf[0]);
            mma_fp16(o[np * 2 + 1], af, &bf[2]);
        }
    }

    const size_t obase = (size_t)(b * KS) * DMODEL + h * DHEAD;
#pragma unroll
    for (int nb = 0; nb < 8; nb++) {
        __half2 p0 = __floats2half2_rn(o[nb][0], o[nb][1]);
        __half2 p1 = __floats2half2_rn(o[nb][2], o[nb][3]);
        *(__half2*)&g_aoh[obase + (size_t)r0 * DMODEL + nb * 8 + scol] = p0;
        *(__half2*)&g_aoh[obase + (size_t)r1 * DMODEL + nb * 8 + scol] = p1;
    }
}

// ===================== gated residual + LayerNorm (proj in fp16) ============
__global__ __launch_bounds__(256) void resid_ln(
    const float* __restrict__ hidden, const float* __restrict__ gamma,
    const float* __restrict__ beta, float* __restrict__ out)
{
    __shared__ float red[2][8];
    const int r = blockIdx.x;
    const float m = g_mask[r];
    const int c = threadIdx.x * 4;
    const size_t base = (size_t)r * DMODEL;

    float4 hv = *(const float4*)(hidden + base + c);
    uint2 pu = *(const uint2*)(&g_projh[base + c]);
    __half2 ph0 = *(__half2*)&pu.x;
    __half2 ph1 = *(__half2*)&pu.y;
    float2 pf0 = __half22float2(ph0);
    float2 pf1 = __half22float2(ph1);
    float v[4] = {hv.x + m * pf0.x, hv.y + m * pf0.y,
                  hv.z + m * pf1.x, hv.w + m * pf1.y};

    float s  = v[0] + v[1] + v[2] + v[3];
    float sq = v[0]*v[0] + v[1]*v[1] + v[2]*v[2] + v[3]*v[3];
#pragma unroll
    for (int o = 16; o; o >>= 1) {
        s  += __shfl_xor_sync(0xffffffffu, s, o);
        sq += __shfl_xor_sync(0xffffffffu, sq, o);
    }
    const int wid = threadIdx.x >> 5, lid = threadIdx.x & 31;
    if (lid == 0) { red[0][wid] = s; red[1][wid] = sq; }
    __syncthreads();
    s = 0.0f; sq = 0.0f;
#pragma unroll
    for (int i = 0; i < 8; i++) { s += red[0][i]; sq += red[1][i]; }

    const float mu  = s  * (1.0f / DMODEL);
    const float var = sq * (1.0f / DMODEL) - mu * mu;
    const float inv = rsqrtf(var + LNEPS);

    float4 g4 = *(const float4*)(gamma + c);
    float4 b4 = *(const float4*)(beta + c);
    float4 o4;
    o4.x = (v[0] - mu) * inv * g4.x + b4.x;
    o4.y = (v[1] - mu) * inv * g4.y + b4.y;
    o4.z = (v[2] - mu) * inv * g4.z + b4.z;
    o4.w = (v[3] - mu) * inv * g4.w + b4.w;
    *(float4*)(out + base + c) = o4;
}

// ===================== launch =====================
extern "C" void kernel_launch(void* const* d_in, const int* in_sizes, int n_in,
                              void* d_out, int out_size)
{
    const float* hidden = (const float*)d_in[0];
    const void*  mask   = d_in[1];
    const float* W[4]   = {(const float*)d_in[2], (const float*)d_in[3],
                           (const float*)d_in[4], (const float*)d_in[5]};
    const float* gamma  = (const float*)d_in[6];
    const float* beta   = (const float*)d_in[7];
    float* out = (float*)d_out;

    __half *phh, *pqkvh, *paoh, *pprojh, *pwh;
    cudaGetSymbolAddress((void**)&phh,    g_hh);
    cudaGetSymbolAddress((void**)&pqkvh,  g_qkvh);
    cudaGetSymbolAddress((void**)&paoh,   g_aoh);
    cudaGetSymbolAddress((void**)&pprojh, g_projh);
    cudaGetSymbolAddress((void**)&pwh,    g_wh);

    cudaFuncSetAttribute(gemm_fp16, cudaFuncAttributeMaxDynamicSharedMemorySize, GEMM_SMEM);

    detect_mask<<<1, 256>>>((const unsigned char*)mask);
    norm_mask<<<NROWS / 256, 256>>>(mask);

    conv_all<<<20480, 256>>>((const float4*)hidden,
        (const float4*)W[0], (const float4*)W[1], (const float4*)W[2], (const float4*)W[3],
        (uint2*)phh, (uint2*)pwh);

    // fused QKV: C[16384 x 3072] = hidden @ [Wq|Wk|Wv]^T
    dim3 gqkv(NQKV / 256, NROWS / 128);      // (12, 128)
    gemm_fp16<<<gqkv, 256, GEMM_SMEM>>>(phh, pwh, pqkvh, NQKV);

    attn_hmma<<<NB * NH, 128>>>();

    dim3 gout(DMODEL / 256, NROWS / 128);    // (4, 128)
    gemm_fp16<<<gout, 256, GEMM_SMEM>>>(paoh, pwh + 3 * (size_t)DMODEL * DMODEL, pprojh, DMODEL);

    resid_ln<<<NROWS, 256>>>(hidden, gamma, beta, out);
}

// round 8
// speedup vs baseline: 1.0747x; 1.0747x over previous
#include <cuda_runtime.h>
#include <cuda_fp16.h>
#include <cstdint>

#define NB      256
#define KS      64
#define DMODEL  1024
#define NQKV    3072
#define NH      16
#define DHEAD   64
#define NROWS   (NB*KS)          // 16384
#define SCALE   0.125f
#define LNEPS   1e-5f

#define SMEM_SWIZZLE_128B(o) ((o) ^ (((o) >> 3) & 0x70))

__device__ __forceinline__ uint32_t smem_to_u32(const void* p) {
    uint32_t a;
    asm("{ .reg .u64 t; cvta.to.shared.u64 t, %1; cvt.u32.u64 %0, t; }" : "=r"(a) : "l"(p));
    return a;
}
__device__ __forceinline__ void ldsm4(uint32_t* r, uint32_t addr) {
    asm volatile("ldmatrix.sync.aligned.m8n8.x4.shared.b16 {%0,%1,%2,%3}, [%4];"
        : "=r"(r[0]), "=r"(r[1]), "=r"(r[2]), "=r"(r[3]) : "r"(addr));
}
__device__ __forceinline__ void ldsm4t(uint32_t* r, uint32_t addr) {
    asm volatile("ldmatrix.sync.aligned.m8n8.x4.trans.shared.b16 {%0,%1,%2,%3}, [%4];"
        : "=r"(r[0]), "=r"(r[1]), "=r"(r[2]), "=r"(r[3]) : "r"(addr));
}
__device__ __forceinline__ void mma_fp16(float* c, const uint32_t* a, const uint32_t* b) {
    asm volatile("mma.sync.aligned.m16n8k16.row.col.f32.f16.f16.f32 "
        "{%0,%1,%2,%3}, {%4,%5,%6,%7}, {%8,%9}, {%0,%1,%2,%3};"
        : "+f"(c[0]), "+f"(c[1]), "+f"(c[2]), "+f"(c[3])
        : "r"(a[0]), "r"(a[1]), "r"(a[2]), "r"(a[3]), "r"(b[0]), "r"(b[1]));
}
#define CP_ASYNC16(dst, src) \
    asm volatile("cp.async.cg.shared.global [%0], [%1], 16;" :: "r"(dst), "l"(src))
#define CP_COMMIT() asm volatile("cp.async.commit_group;" ::: "memory")
#define CP_WAIT(n)  asm volatile("cp.async.wait_group %0;" :: "n"(n) : "memory")

// ===================== scratch =====================
__device__ float  g_mask[NROWS];
__device__ int    g_masktype;
__device__ __half g_hh[NROWS*DMODEL];      // hidden fp16
__device__ __half g_qkvh[NROWS*NQKV];      // fused QKV output, row stride 3072
__device__ __half g_aoh[NROWS*DMODEL];     // attention out fp16
__device__ __half g_projh[NROWS*DMODEL];   // W_o projection fp16
__device__ __half g_wh[4*DMODEL*DMODEL];   // weights fp16 (Wq|Wk|Wv|Wo)

// ===================== mask handling =====================
__global__ void detect_mask(const unsigned char* __restrict__ p) {
    __shared__ int sflt, smis;
    if (threadIdx.x == 0) { sflt = 0; smis = 0; }
    __syncthreads();
    int f = 0, ms = 0;
    for (int i = threadIdx.x; i < NROWS; i += 256) {
        unsigned char v = p[i];
        if (v > 1) f = 1;
        if (v != 0 && (i & 3)) ms = 1;
    }
    if (f)  atomicOr(&sflt, 1);
    if (ms) atomicOr(&smis, 1);
    __syncthreads();
    if (threadIdx.x == 0) g_masktype = sflt ? 0 : (smis ? 1 : 2);
}

__global__ void norm_mask(const void* __restrict__ p) {
    int i = blockIdx.x * blockDim.x + threadIdx.x;
    if (i >= NROWS) return;
    int t = g_masktype;
    float m;
    if (t == 0)      m = (((const float*)p)[i] != 0.0f) ? 1.0f : 0.0f;
    else if (t == 1) m = (((const unsigned char*)p)[i] != 0) ? 1.0f : 0.0f;
    else             m = (((const int*)p)[i] != 0) ? 1.0f : 0.0f;
    g_mask[i] = m;
}

// ===================== merged fp32 -> fp16 convert (hidden + 4 weights) ======
__global__ __launch_bounds__(256) void conv_all(
    const float4* __restrict__ hidden,
    const float4* __restrict__ w0, const float4* __restrict__ w1,
    const float4* __restrict__ w2, const float4* __restrict__ w3,
    uint2* __restrict__ dh, uint2* __restrict__ dw)
{
    const int bid = blockIdx.x;
    const float4* src;
    uint2* dst;
    int i;
    if (bid < 16384) {
        i = bid * 256 + threadIdx.x;
        src = hidden; dst = dh;
    } else {
        const int t = bid - 16384;
        const int w = t >> 10;
        src = (w == 0) ? w0 : (w == 1) ? w1 : (w == 2) ? w2 : w3;
        dst = dw + (size_t)w * (DMODEL * DMODEL / 4);
        i = (t & 1023) * 256 + threadIdx.x;
    }
    float4 v = src[i];
    __half2 a = __floats2half2_rn(v.x, v.y);
    __half2 b = __floats2half2_rn(v.z, v.w);
    uint2 u;
    u.x = *(uint32_t*)&a; u.y = *(uint32_t*)&b;
    dst[i] = u;
}

// ===================== fp16 HMMA GEMM: C = A @ B^T, fp16 out ================
// CTA tile 128x128, warp tile 64x32 (8 warps, 2x4), K-tile 64, 3-stage,
// 2 CTAs/SM (96KB smem each).
#define STAGE_BYTES 32768        // A 16K | B 16K
#define GSTAGES 3
#define GEMM_SMEM (GSTAGES * STAGE_BYTES)
#define NKT 16

__device__ __forceinline__ void load_stage_async(
    uint32_t sbase,
    const __half* __restrict__ A, const __half* __restrict__ B,
    int m0, int n0, int k0, int tid)
{
#pragma unroll
    for (int i = 0; i < 8; i++) {
        const int idx = tid + i * 256;
        const int buf = idx >> 10;
        const int j = idx & 1023;
        const int r = j >> 3, cc = j & 7;
        uint32_t so = sbase + buf * 16384 + SMEM_SWIZZLE_128B((uint32_t)(r * 128 + cc * 16));
        const __half* src = (buf == 0)
            ? A + (size_t)(m0 + r) * DMODEL + k0 + cc * 8
            : B + (size_t)(n0 + r) * DMODEL + k0 + cc * 8;
        CP_ASYNC16(so, src);
    }
}

__global__ __launch_bounds__(256, 2) void gemm_fp16(
    const __half* __restrict__ A, const __half* __restrict__ B,
    __half* __restrict__ C, int ldC)
{
    extern __shared__ char sm[];
    const uint32_t smem_base = smem_to_u32(sm);
    const int tid  = threadIdx.x;
    const int lane = tid & 31;
    const int wid  = tid >> 5;
    const int warp_m = wid & 1;
    const int warp_n = wid >> 1;
    const int m0 = blockIdx.y * 128;
    const int n0 = blockIdx.x * 128;
    const int m0w = warp_m * 64, n0w = warp_n * 32;

    float c[4][4][4];
#pragma unroll
    for (int mi = 0; mi < 4; mi++)
#pragma unroll
        for (int ni = 0; ni < 4; ni++)
#pragma unroll
            for (int e = 0; e < 4; e++) c[mi][ni][e] = 0.0f;

    load_stage_async(smem_base + 0 * STAGE_BYTES, A, B, m0, n0, 0, tid);
    CP_COMMIT();
    load_stage_async(smem_base + 1 * STAGE_BYTES, A, B, m0, n0, 64, tid);
    CP_COMMIT();

    const int arow  = m0w + (lane & 15);
    const int abyt  = ((lane >> 4) & 1) * 16;
    const int brow0 = n0w + ((lane >> 4) & 1) * 8 + (lane & 7);
    const int bbyt  = ((lane >> 3) & 1) * 16;

    int cur = 0;
    for (int kt = 0; kt < NKT; kt++) {
        CP_WAIT(1);
        __syncthreads();
        if (kt + 2 < NKT) {
            const int nxt = (kt + 2) % GSTAGES;
            load_stage_async(smem_base + nxt * STAGE_BYTES, A, B, m0, n0, (kt + 2) * 64, tid);
        }
        CP_COMMIT();

        const uint32_t sb = smem_base + cur * STAGE_BYTES;
#pragma unroll
        for (int ks = 0; ks < 4; ks++) {
            uint32_t af[4][4];
#pragma unroll
            for (int mi = 0; mi < 4; mi++) {
                uint32_t off = SMEM_SWIZZLE_128B((uint32_t)((arow + mi * 16) * 128 + ks * 32 + abyt));
                ldsm4(af[mi], sb + off);
            }
            uint32_t bf[2][4];
#pragma unroll
            for (int g = 0; g < 2; g++) {
                uint32_t off = SMEM_SWIZZLE_128B((uint32_t)((brow0 + g * 16) * 128 + ks * 32 + bbyt));
                ldsm4(bf[g], sb + 16384 + off);
            }
#pragma unroll
            for (int mi = 0; mi < 4; mi++)
#pragma unroll
                for (int ni = 0; ni < 4; ni++)
                    mma_fp16(c[mi][ni], af[mi], &bf[ni >> 1][(ni & 1) * 2]);
        }
        cur = (cur + 1) % GSTAGES;
        __syncthreads();
    }

#pragma unroll
    for (int mi = 0; mi < 4; mi++) {
        const int r0 = m0 + m0w + mi * 16 + (lane >> 2);
#pragma unroll
        for (int ni = 0; ni < 4; ni++) {
            const int cc = n0 + n0w + ni * 8 + (lane & 3) * 2;
            __half2 p0 = __floats2half2_rn(c[mi][ni][0], c[mi][ni][1]);
            __half2 p1 = __floats2half2_rn(c[mi][ni][2], c[mi][ni][3]);
            *(__half2*)(C + (size_t)r0 * ldC + cc)       = p0;
            *(__half2*)(C + (size_t)(r0 + 8) * ldC + cc) = p1;
        }
    }
}

// ===================== HMMA attention: one CTA (128 thr) per (b,h) ==========
__global__ __launch_bounds__(128) void attn_hmma() {
    __shared__ __half sQ[64 * 64];
    __shared__ __half sK[64 * 64];
    __shared__ __half sV[64 * 64];
    __shared__ __half sS[64 * 64];

    const int bh   = blockIdx.x;
    const int b    = bh >> 4;
    const int h    = bh & 15;
    const int tid  = threadIdx.x;
    const int lane = tid & 31;
    const int wid  = tid >> 5;

    const uint32_t q_s = smem_to_u32(sQ);
    const uint32_t k_s = smem_to_u32(sK);
    const uint32_t v_s = smem_to_u32(sV);
    const uint32_t s_s = smem_to_u32(sS);

    const size_t qbase = (size_t)(b * KS) * NQKV + h * DHEAD;

#pragma unroll
    for (int i = 0; i < 4; i++) {
        int idx = tid + i * 128;
        int r = idx >> 3, ch = idx & 7;
        size_t ga = qbase + (size_t)r * NQKV + ch * 8;
        uint32_t so = SMEM_SWIZZLE_128B((uint32_t)(r * 128 + ch * 16));
        *(uint4*)((char*)sQ + so) = *(const uint4*)&g_qkvh[ga];
        *(uint4*)((char*)sK + so) = *(const uint4*)&g_qkvh[ga + 1024];
        *(uint4*)((char*)sV + so) = *(const uint4*)&g_qkvh[ga + 2048];
    }
    __syncthreads();

    float c[8][4];
#pragma unroll
    for (int nb = 0; nb < 8; nb++)
#pragma unroll
        for (int e = 0; e < 4; e++) c[nb][e] = 0.0f;

    const int arow = wid * 16 + (lane & 15);
    const int abyt = ((lane >> 4) & 1) * 16;
    const int brow = ((lane >> 4) & 1) * 8 + (lane & 7);
    const int bbyt = ((lane >> 3) & 1) * 16;

#pragma unroll
    for (int ks = 0; ks < 4; ks++) {
        uint32_t af[4];
        ldsm4(af, q_s + SMEM_SWIZZLE_128B((uint32_t)(arow * 128 + ks * 32 + abyt)));
        uint32_t bf[4][4];
#pragma unroll
        for (int p = 0; p < 4; p++)
            ldsm4(bf[p], k_s + SMEM_SWIZZLE_128B((uint32_t)((p * 16 + brow) * 128 + ks * 32 + bbyt)));
#pragma unroll
        for (int nb = 0; nb < 8; nb++)
            mma_fp16(c[nb], af, &bf[nb >> 1][(nb & 1) * 2]);
    }

    const int r0 = wid * 16 + (lane >> 2);
    const int r1 = r0 + 8;
    float m0 = -1e30f, m1 = -1e30f;
#pragma unroll
    for (int nb = 0; nb < 8; nb++) {
#pragma unroll
        for (int e = 0; e < 4; e++) c[nb][e] *= SCALE;
        m0 = fmaxf(m0, fmaxf(c[nb][0], c[nb][1]));
        m1 = fmaxf(m1, fmaxf(c[nb][2], c[nb][3]));
    }
    m0 = fmaxf(m0, __shfl_xor_sync(0xffffffffu, m0, 1));
    m0 = fmaxf(m0, __shfl_xor_sync(0xffffffffu, m0, 2));
    m1 = fmaxf(m1, __shfl_xor_sync(0xffffffffu, m1, 1));
    m1 = fmaxf(m1, __shfl_xor_sync(0xffffffffu, m1, 2));
    float s0 = 0.0f, s1 = 0.0f;
#pragma unroll
    for (int nb = 0; nb < 8; nb++) {
        c[nb][0] = __expf(c[nb][0] - m0); s0 += c[nb][0];
        c[nb][1] = __expf(c[nb][1] - m0); s0 += c[nb][1];
        c[nb][2] = __expf(c[nb][2] - m1); s1 += c[nb][2];
        c[nb][3] = __expf(c[nb][3] - m1); s1 += c[nb][3];
    }
    s0 += __shfl_xor_sync(0xffffffffu, s0, 1);
    s0 += __shfl_xor_sync(0xffffffffu, s0, 2);
    s1 += __shfl_xor_sync(0xffffffffu, s1, 1);
    s1 += __shfl_xor_sync(0xffffffffu, s1, 2);
    const float w0 = g_mask[b * KS + r0] / s0;
    const float w1 = g_mask[b * KS + r1] / s1;

    const int scol = (lane & 3) * 2;
#pragma unroll
    for (int nb = 0; nb < 8; nb++) {
        __half2 p0 = __floats2half2_rn(c[nb][0] * w0, c[nb][1] * w0);
        __half2 p1 = __floats2half2_rn(c[nb][2] * w1, c[nb][3] * w1);
        *(__half2*)((char*)sS + SMEM_SWIZZLE_128B((uint32_t)(r0 * 128 + (nb * 8 + scol) * 2))) = p0;
        *(__half2*)((char*)sS + SMEM_SWIZZLE_128B((uint32_t)(r1 * 128 + (nb * 8 + scol) * 2))) = p1;
    }
    __syncwarp();

    float o[8][4];
#pragma unroll
    for (int nb = 0; nb < 8; nb++)
#pragma unroll
        for (int e = 0; e < 4; e++) o[nb][e] = 0.0f;

    const int g  = lane >> 3;
    const int gr = lane & 7;
#pragma unroll
    for (int ks = 0; ks < 4; ks++) {
        uint32_t af[4];
        ldsm4(af, s_s + SMEM_SWIZZLE_128B((uint32_t)(arow * 128 + ks * 32 + abyt)));
#pragma unroll
        for (int np = 0; np < 4; np++) {
            uint32_t bf[4];
            const int krow = ks * 16 + (g & 1) * 8 + gr;
            const int dcol = np * 16 + (g >> 1) * 8;
            ldsm4t(bf, v_s + SMEM_SWIZZLE_128B((uint32_t)(krow * 128 + dcol * 2)));
            mma_fp16(o[np * 2 + 0], af, &bf[0]);
            mma_fp16(o[np * 2 + 1], af, &bf[2]);
        }
    }

    const size_t obase = (size_t)(b * KS) * DMODEL + h * DHEAD;
#pragma unroll
    for (int nb = 0; nb < 8; nb++) {
        __half2 p0 = __floats2half2_rn(o[nb][0], o[nb][1]);
        __half2 p1 = __floats2half2_rn(o[nb][2], o[nb][3]);
        *(__half2*)&g_aoh[obase + (size_t)r0 * DMODEL + nb * 8 + scol] = p0;
        *(__half2*)&g_aoh[obase + (size_t)r1 * DMODEL + nb * 8 + scol] = p1;
    }
}

// ===================== gated residual + LayerNorm (proj in fp16) ============
__global__ __launch_bounds__(256) void resid_ln(
    const float* __restrict__ hidden, const float* __restrict__ gamma,
    const float* __restrict__ beta, float* __restrict__ out)
{
    __shared__ float red[2][8];
    const int r = blockIdx.x;
    const float m = g_mask[r];
    const int c = threadIdx.x * 4;
    const size_t base = (size_t)r * DMODEL;

    float4 hv = *(const float4*)(hidden + base + c);
    uint2 pu = *(const uint2*)(&g_projh[base + c]);
    __half2 ph0 = *(__half2*)&pu.x;
    __half2 ph1 = *(__half2*)&pu.y;
    float2 pf0 = __half22float2(ph0);
    float2 pf1 = __half22float2(ph1);
    float v[4] = {hv.x + m * pf0.x, hv.y + m * pf0.y,
                  hv.z + m * pf1.x, hv.w + m * pf1.y};

    float s  = v[0] + v[1] + v[2] + v[3];
    float sq = v[0]*v[0] + v[1]*v[1] + v[2]*v[2] + v[3]*v[3];
#pragma unroll
    for (int o = 16; o; o >>= 1) {
        s  += __shfl_xor_sync(0xffffffffu, s, o);
        sq += __shfl_xor_sync(0xffffffffu, sq, o);
    }
    const int wid = threadIdx.x >> 5, lid = threadIdx.x & 31;
    if (lid == 0) { red[0][wid] = s; red[1][wid] = sq; }
    __syncthreads();
    s = 0.0f; sq = 0.0f;
#pragma unroll
    for (int i = 0; i < 8; i++) { s += red[0][i]; sq += red[1][i]; }

    const float mu  = s  * (1.0f / DMODEL);
    const float var = sq * (1.0f / DMODEL) - mu * mu;
    const float inv = rsqrtf(var + LNEPS);

    float4 g4 = *(const float4*)(gamma + c);
    float4 b4 = *(const float4*)(beta + c);
    float4 o4;
    o4.x = (v[0] - mu) * inv * g4.x + b4.x;
    o4.y = (v[1] - mu) * inv * g4.y + b4.y;
    o4.z = (v[2] - mu) * inv * g4.z + b4.z;
    o4.w = (v[3] - mu) * inv * g4.w + b4.w;
    *(float4*)(out + base + c) = o4;
}

// ===================== launch =====================
extern "C" void kernel_launch(void* const* d_in, const int* in_sizes, int n_in,
                              void* d_out, int out_size)
{
    const float* hidden = (const float*)d_in[0];
    const void*  mask   = d_in[1];
    const float* W[4]   = {(const float*)d_in[2], (const float*)d_in[3],
                           (const float*)d_in[4], (const float*)d_in[5]};
    const float* gamma  = (const float*)d_in[6];
    const float* beta   = (const float*)d_in[7];
    float* out = (float*)d_out;

    __half *phh, *pqkvh, *paoh, *pprojh, *pwh;
    cudaGetSymbolAddress((void**)&phh,    g_hh);
    cudaGetSymbolAddress((void**)&pqkvh,  g_qkvh);
    cudaGetSymbolAddress((void**)&paoh,   g_aoh);
    cudaGetSymbolAddress((void**)&pprojh, g_projh);
    cudaGetSymbolAddress((void**)&pwh,    g_wh);

    cudaFuncSetAttribute(gemm_fp16, cudaFuncAttributeMaxDynamicSharedMemorySize, GEMM_SMEM);

    detect_mask<<<1, 256>>>((const unsigned char*)mask);
    norm_mask<<<NROWS / 256, 256>>>(mask);

    conv_all<<<20480, 256>>>((const float4*)hidden,
        (const float4*)W[0], (const float4*)W[1], (const float4*)W[2], (const float4*)W[3],
        (uint2*)phh, (uint2*)pwh);

    // fused QKV: C[16384 x 3072] = hidden @ [Wq|Wk|Wv]^T, one launch
    dim3 gqkv(NQKV / 128, NROWS / 128);      // (24, 128) = 3072 CTAs
    gemm_fp16<<<gqkv, 256, GEMM_SMEM>>>(phh, pwh, pqkvh, NQKV);

    attn_hmma<<<NB * NH, 128>>>();

    dim3 gout(DMODEL / 128, NROWS / 128);    // (8, 128)
    gemm_fp16<<<gout, 256, GEMM_SMEM>>>(paoh, pwh + 3 * (size_t)DMODEL * DMODEL, pprojh, DMODEL);

    resid_ln<<<NROWS, 256>>>(hidden, gamma, beta, out);
}

// round 11
// speedup vs baseline: 1.0948x; 1.0187x over previous
#include <cuda_runtime.h>
#include <cuda_fp16.h>
#include <cstdint>

#define NB      256
#define KS      64
#define DMODEL  1024
#define NQKV    3072
#define NH      16
#define DHEAD   64
#define NROWS   (NB*KS)          // 16384
#define SCALE   0.125f
#define LNEPS   1e-5f

#define SMEM_SWIZZLE_128B(o) ((o) ^ (((o) >> 3) & 0x70))

__device__ __forceinline__ uint32_t smem_to_u32(const void* p) {
    uint32_t a;
    asm("{ .reg .u64 t; cvta.to.shared.u64 t, %1; cvt.u32.u64 %0, t; }" : "=r"(a) : "l"(p));
    return a;
}
__device__ __forceinline__ void ldsm4(uint32_t* r, uint32_t addr) {
    asm volatile("ldmatrix.sync.aligned.m8n8.x4.shared.b16 {%0,%1,%2,%3}, [%4];"
        : "=r"(r[0]), "=r"(r[1]), "=r"(r[2]), "=r"(r[3]) : "r"(addr));
}
__device__ __forceinline__ void ldsm4t(uint32_t* r, uint32_t addr) {
    asm volatile("ldmatrix.sync.aligned.m8n8.x4.trans.shared.b16 {%0,%1,%2,%3}, [%4];"
        : "=r"(r[0]), "=r"(r[1]), "=r"(r[2]), "=r"(r[3]) : "r"(addr));
}
__device__ __forceinline__ void mma_fp16(float* c, const uint32_t* a, const uint32_t* b) {
    asm volatile("mma.sync.aligned.m16n8k16.row.col.f32.f16.f16.f32 "
        "{%0,%1,%2,%3}, {%4,%5,%6,%7}, {%8,%9}, {%0,%1,%2,%3};"
        : "+f"(c[0]), "+f"(c[1]), "+f"(c[2]), "+f"(c[3])
        : "r"(a[0]), "r"(a[1]), "r"(a[2]), "r"(a[3]), "r"(b[0]), "r"(b[1]));
}
#define CP_ASYNC16(dst, src) \
    asm volatile("cp.async.cg.shared.global [%0], [%1], 16;" :: "r"(dst), "l"(src))
#define CP_COMMIT() asm volatile("cp.async.commit_group;" ::: "memory")
#define CP_WAIT(n)  asm volatile("cp.async.wait_group %0;" :: "n"(n) : "memory")

// ===================== scratch =====================
__device__ float  g_mask[NROWS];
__device__ int    g_masktype;
__device__ __half g_hh[NROWS*DMODEL];
__device__ __half g_qkvh[NROWS*NQKV];
__device__ __half g_aoh[NROWS*DMODEL];
__device__ __half g_projh[NROWS*DMODEL];
__device__ __half g_wh[4*DMODEL*DMODEL];

// ===================== mask handling =====================
__global__ void detect_mask(const unsigned char* __restrict__ p) {
    __shared__ int sflt, smis;
    if (threadIdx.x == 0) { sflt = 0; smis = 0; }
    __syncthreads();
    int f = 0, ms = 0;
    for (int i = threadIdx.x; i < NROWS; i += 256) {
        unsigned char v = p[i];
        if (v > 1) f = 1;
        if (v != 0 && (i & 3)) ms = 1;
    }
    if (f)  atomicOr(&sflt, 1);
    if (ms) atomicOr(&smis, 1);
    __syncthreads();
    if (threadIdx.x == 0) g_masktype = sflt ? 0 : (smis ? 1 : 2);
}

__global__ void norm_mask(const void* __restrict__ p) {
    int i = blockIdx.x * blockDim.x + threadIdx.x;
    if (i >= NROWS) return;
    int t = g_masktype;
    float m;
    if (t == 0)      m = (((const float*)p)[i] != 0.0f) ? 1.0f : 0.0f;
    else if (t == 1) m = (((const unsigned char*)p)[i] != 0) ? 1.0f : 0.0f;
    else             m = (((const int*)p)[i] != 0) ? 1.0f : 0.0f;
    g_mask[i] = m;
}

// ===================== merged fp32 -> fp16 convert =====================
__global__ __launch_bounds__(256) void conv_all(
    const float4* __restrict__ hidden,
    const float4* __restrict__ w0, const float4* __restrict__ w1,
    const float4* __restrict__ w2, const float4* __restrict__ w3,
    uint2* __restrict__ dh, uint2* __restrict__ dw)
{
    const int bid = blockIdx.x;
    const float4* src;
    uint2* dst;
    int i;
    if (bid < 16384) {
        i = bid * 256 + threadIdx.x;
        src = hidden; dst = dh;
    } else {
        const int t = bid - 16384;
        const int w = t >> 10;
        src = (w == 0) ? w0 : (w == 1) ? w1 : (w == 2) ? w2 : w3;
        dst = dw + (size_t)w * (DMODEL * DMODEL / 4);
        i = (t & 1023) * 256 + threadIdx.x;
    }
    float4 v = src[i];
    __half2 a = __floats2half2_rn(v.x, v.y);
    __half2 b = __floats2half2_rn(v.z, v.w);
    uint2 u;
    u.x = *(uint32_t*)&a; u.y = *(uint32_t*)&b;
    dst[i] = u;
}

// ===================== fp16 HMMA GEMM: C = A @ B^T, fp16 out ================
#define STAGE_BYTES 32768
#define GSTAGES 3
#define GEMM_SMEM (GSTAGES * STAGE_BYTES)
#define NKT 16

__device__ __forceinline__ void load_stage_async(
    uint32_t sbase,
    const __half* __restrict__ A, const __half* __restrict__ B,
    int m0, int n0, int k0, int tid)
{
#pragma unroll
    for (int i = 0; i < 8; i++) {
        const int idx = tid + i * 256;
        const int buf = idx >> 10;
        const int j = idx & 1023;
        const int r = j >> 3, cc = j & 7;
        uint32_t so = sbase + buf * 16384 + SMEM_SWIZZLE_128B((uint32_t)(r * 128 + cc * 16));
        const __half* src = (buf == 0)
            ? A + (size_t)(m0 + r) * DMODEL + k0 + cc * 8
            : B + (size_t)(n0 + r) * DMODEL + k0 + cc * 8;
        CP_ASYNC16(so, src);
    }
}

__global__ __launch_bounds__(256, 2) void gemm_fp16(
    const __half* __restrict__ A, const __half* __restrict__ B,
    __half* __restrict__ C, int ldC)
{
    extern __shared__ char sm[];
    const uint32_t smem_base = smem_to_u32(sm);
    const int tid  = threadIdx.x;
    const int lane = tid & 31;
    const int wid  = tid >> 5;
    const int warp_m = wid & 1;
    const int warp_n = wid >> 1;
    const int m0 = blockIdx.y * 128;
    const int n0 = blockIdx.x * 128;
    const int m0w = warp_m * 64, n0w = warp_n * 32;

    float c[4][4][4];
#pragma unroll
    for (int mi = 0; mi < 4; mi++)
#pragma unroll
        for (int ni = 0; ni < 4; ni++)
#pragma unroll
            for (int e = 0; e < 4; e++) c[mi][ni][e] = 0.0f;

    load_stage_async(smem_base + 0 * STAGE_BYTES, A, B, m0, n0, 0, tid);
    CP_COMMIT();
    load_stage_async(smem_base + 1 * STAGE_BYTES, A, B, m0, n0, 64, tid);
    CP_COMMIT();

    const int arow  = m0w + (lane & 15);
    const int abyt  = ((lane >> 4) & 1) * 16;
    const int brow0 = n0w + ((lane >> 4) & 1) * 8 + (lane & 7);
    const int bbyt  = ((lane >> 3) & 1) * 16;

    int cur = 0;
    for (int kt = 0; kt < NKT; kt++) {
        CP_WAIT(1);
        __syncthreads();
        // Safe without a tail barrier: this load targets stage (kt+2)%3 ==
        // (kt-1)%3, whose compute every warp finished before reaching the
        // barrier above.
        if (kt + 2 < NKT) {
            const int nxt = (kt + 2) % GSTAGES;
            load_stage_async(smem_base + nxt * STAGE_BYTES, A, B, m0, n0, (kt + 2) * 64, tid);
        }
        CP_COMMIT();

        const uint32_t sb = smem_base + cur * STAGE_BYTES;
#pragma unroll
        for (int ks = 0; ks < 4; ks++) {
            uint32_t af[4][4];
#pragma unroll
            for (int mi = 0; mi < 4; mi++) {
                uint32_t off = SMEM_SWIZZLE_128B((uint32_t)((arow + mi * 16) * 128 + ks * 32 + abyt));
                ldsm4(af[mi], sb + off);
            }
            uint32_t bf[2][4];
#pragma unroll
            for (int g = 0; g < 2; g++) {
                uint32_t off = SMEM_SWIZZLE_128B((uint32_t)((brow0 + g * 16) * 128 + ks * 32 + bbyt));
                ldsm4(bf[g], sb + 16384 + off);
            }
#pragma unroll
            for (int mi = 0; mi < 4; mi++)
#pragma unroll
                for (int ni = 0; ni < 4; ni++)
                    mma_fp16(c[mi][ni], af[mi], &bf[ni >> 1][(ni & 1) * 2]);
        }
        cur = (cur + 1) % GSTAGES;
    }

#pragma unroll
    for (int mi = 0; mi < 4; mi++) {
        const int r0 = m0 + m0w + mi * 16 + (lane >> 2);
#pragma unroll
        for (int ni = 0; ni < 4; ni++) {
            const int cc = n0 + n0w + ni * 8 + (lane & 3) * 2;
            __half2 p0 = __floats2half2_rn(c[mi][ni][0], c[mi][ni][1]);
            __half2 p1 = __floats2half2_rn(c[mi][ni][2], c[mi][ni][3]);
            *(__half2*)(C + (size_t)r0 * ldC + cc)       = p0;
            *(__half2*)(C + (size_t)(r0 + 8) * ldC + cc) = p1;
        }
    }
}

// ===================== HMMA attention: 2 heads per CTA (256 thr) ============
// warps 0-3: head h0, warps 4-7: head h0+1. Per-head 8KB smem regions.
#define ATTN_SMEM (8 * 8192)     // Q,K,V,S x 2 heads x 8KB

__global__ __launch_bounds__(256) void attn_hmma() {
    extern __shared__ char asm_[];
    const int bh2  = blockIdx.x;       // 0..2047
    const int b    = bh2 >> 3;
    const int h0   = (bh2 & 7) * 2;
    const int tid  = threadIdx.x;
    const int lane = tid & 31;
    const int wid  = tid >> 5;
    const int wh   = wid >> 2;         // head select
    const int wl   = wid & 3;          // warp within head

    // generic pointers for C++ stores, u32 shared addresses for ldmatrix
    char* const q_p = asm_ + wh * 8192;
    char* const k_p = asm_ + 16384 + wh * 8192;
    char* const v_p = asm_ + 32768 + wh * 8192;
    char* const s_p = asm_ + 49152 + wh * 8192;
    const uint32_t q_s = smem_to_u32(q_p);
    const uint32_t k_s = smem_to_u32(k_p);
    const uint32_t v_s = smem_to_u32(v_p);
    const uint32_t s_s = smem_to_u32(s_p);

    // load Q,K,V for both heads: per row, 256B contiguous (2 heads x 128B)
    const size_t qbase = (size_t)(b * KS) * NQKV + h0 * DHEAD;
#pragma unroll
    for (int i = 0; i < 4; i++) {
        int idx = tid + i * 256;           // 0..1023 chunks (64 rows x 16)
        int r = idx >> 4, c16 = idx & 15;
        int hd = c16 >> 3, ch = c16 & 7;
        size_t ga = qbase + (size_t)r * NQKV + c16 * 8;
        uint32_t so = hd * 8192 + SMEM_SWIZZLE_128B((uint32_t)(r * 128 + ch * 16));
        *(uint4*)(asm_ + so)          = *(const uint4*)&g_qkvh[ga];
        *(uint4*)(asm_ + 16384 + so)  = *(const uint4*)&g_qkvh[ga + 1024];
        *(uint4*)(asm_ + 32768 + so)  = *(const uint4*)&g_qkvh[ga + 2048];
    }
    __syncthreads();

    // ---- S = Q @ K^T ----
    float c[8][4];
#pragma unroll
    for (int nb = 0; nb < 8; nb++)
#pragma unroll
        for (int e = 0; e < 4; e++) c[nb][e] = 0.0f;

    const int arow = wl * 16 + (lane & 15);
    const int abyt = ((lane >> 4) & 1) * 16;
    const int brow = ((lane >> 4) & 1) * 8 + (lane & 7);
    const int bbyt = ((lane >> 3) & 1) * 16;

#pragma unroll
    for (int ks = 0; ks < 4; ks++) {
        uint32_t af[4];
        ldsm4(af, q_s + SMEM_SWIZZLE_128B((uint32_t)(arow * 128 + ks * 32 + abyt)));
        uint32_t bf[4][4];
#pragma unroll
        for (int p = 0; p < 4; p++)
            ldsm4(bf[p], k_s + SMEM_SWIZZLE_128B((uint32_t)((p * 16 + brow) * 128 + ks * 32 + bbyt)));
#pragma unroll
        for (int nb = 0; nb < 8; nb++)
            mma_fp16(c[nb], af, &bf[nb >> 1][(nb & 1) * 2]);
    }

    // ---- softmax + mask (mask depends on sequence row only) ----
    const int r0 = wl * 16 + (lane >> 2);
    const int r1 = r0 + 8;
    float m0 = -1e30f, m1 = -1e30f;
#pragma unroll
    for (int nb = 0; nb < 8; nb++) {
#pragma unroll
        for (int e = 0; e < 4; e++) c[nb][e] *= SCALE;
        m0 = fmaxf(m0, fmaxf(c[nb][0], c[nb][1]));
        m1 = fmaxf(m1, fmaxf(c[nb][2], c[nb][3]));
    }
    m0 = fmaxf(m0, __shfl_xor_sync(0xffffffffu, m0, 1));
    m0 = fmaxf(m0, __shfl_xor_sync(0xffffffffu, m0, 2));
    m1 = fmaxf(m1, __shfl_xor_sync(0xffffffffu, m1, 1));
    m1 = fmaxf(m1, __shfl_xor_sync(0xffffffffu, m1, 2));
    float s0 = 0.0f, s1 = 0.0f;
#pragma unroll
    for (int nb = 0; nb < 8; nb++) {
        c[nb][0] = __expf(c[nb][0] - m0); s0 += c[nb][0];
        c[nb][1] = __expf(c[nb][1] - m0); s0 += c[nb][1];
        c[nb][2] = __expf(c[nb][2] - m1); s1 += c[nb][2];
        c[nb][3] = __expf(c[nb][3] - m1); s1 += c[nb][3];
    }
    s0 += __shfl_xor_sync(0xffffffffu, s0, 1);
    s0 += __shfl_xor_sync(0xffffffffu, s0, 2);
    s1 += __shfl_xor_sync(0xffffffffu, s1, 1);
    s1 += __shfl_xor_sync(0xffffffffu, s1, 2);
    const float w0 = g_mask[b * KS + r0] / s0;
    const float w1 = g_mask[b * KS + r1] / s1;

    const int scol = (lane & 3) * 2;
#pragma unroll
    for (int nb = 0; nb < 8; nb++) {
        __half2 p0 = __floats2half2_rn(c[nb][0] * w0, c[nb][1] * w0);
        __half2 p1 = __floats2half2_rn(c[nb][2] * w1, c[nb][3] * w1);
        *(__half2*)(s_p + SMEM_SWIZZLE_128B((uint32_t)(r0 * 128 + (nb * 8 + scol) * 2))) = p0;
        *(__half2*)(s_p + SMEM_SWIZZLE_128B((uint32_t)(r1 * 128 + (nb * 8 + scol) * 2))) = p1;
    }
    __syncwarp();

    // ---- O = S @ V ----
    float o[8][4];
#pragma unroll
    for (int nb = 0; nb < 8; nb++)
#pragma unroll
        for (int e = 0; e < 4; e++) o[nb][e] = 0.0f;

    const int g  = lane >> 3;
    const int gr = lane & 7;
#pragma unroll
    for (int ks = 0; ks < 4; ks++) {
        uint32_t af[4];
        ldsm4(af, s_s + SMEM_SWIZZLE_128B((uint32_t)(arow * 128 + ks * 32 + abyt)));
#pragma unroll
        for (int np = 0; np < 4; np++) {
            uint32_t bf[4];
            const int krow = ks * 16 + (g & 1) * 8 + gr;
            const int dcol = np * 16 + (g >> 1) * 8;
            ldsm4t(bf, v_s + SMEM_SWIZZLE_128B((uint32_t)(krow * 128 + dcol * 2)));
            mma_fp16(o[np * 2 + 0], af, &bf[0]);
            mma_fp16(o[np * 2 + 1], af, &bf[2]);
        }
    }

    const int h = h0 + wh;
    const size_t obase = (size_t)(b * KS) * DMODEL + h * DHEAD;
#pragma unroll
    for (int nb = 0; nb < 8; nb++) {
        __half2 p0 = __floats2half2_rn(o[nb][0], o[nb][1]);
        __half2 p1 = __floats2half2_rn(o[nb][2], o[nb][3]);
        *(__half2*)&g_aoh[obase + (size_t)r0 * DMODEL + nb * 8 + scol] = p0;
        *(__half2*)&g_aoh[obase + (size_t)r1 * DMODEL + nb * 8 + scol] = p1;
    }
}

// ===================== gated residual + LayerNorm ============
__global__ __launch_bounds__(256) void resid_ln(
    const float* __restrict__ hidden, const float* __restrict__ gamma,
    const float* __restrict__ beta, float* __restrict__ out)
{
    __shared__ float red[2][8];
    const int r = blockIdx.x;
    const float m = g_mask[r];
    const int c = threadIdx.x * 4;
    const size_t base = (size_t)r * DMODEL;

    float4 hv = *(const float4*)(hidden + base + c);
    uint2 pu = *(const uint2*)(&g_projh[base + c]);
    __half2 ph0 = *(__half2*)&pu.x;
    __half2 ph1 = *(__half2*)&pu.y;
    float2 pf0 = __half22float2(ph0);
    float2 pf1 = __half22float2(ph1);
    float v[4] = {hv.x + m * pf0.x, hv.y + m * pf0.y,
                  hv.z + m * pf1.x, hv.w + m * pf1.y};

    float s  = v[0] + v[1] + v[2] + v[3];
    float sq = v[0]*v[0] + v[1]*v[1] + v[2]*v[2] + v[3]*v[3];
#pragma unroll
    for (int o = 16; o; o >>= 1) {
        s  += __shfl_xor_sync(0xffffffffu, s, o);
        sq += __shfl_xor_sync(0xffffffffu, sq, o);
    }
    const int wid = threadIdx.x >> 5, lid = threadIdx.x & 31;
    if (lid == 0) { red[0][wid] = s; red[1][wid] = sq; }
    __syncthreads();
    s = 0.0f; sq = 0.0f;
#pragma unroll
    for (int i = 0; i < 8; i++) { s += red[0][i]; sq += red[1][i]; }

    const float mu  = s  * (1.0f / DMODEL);
    const float var = sq * (1.0f / DMODEL) - mu * mu;
    const float inv = rsqrtf(var + LNEPS);

    float4 g4 = *(const float4*)(gamma + c);
    float4 b4 = *(const float4*)(beta + c);
    float4 o4;
    o4.x = (v[0] - mu) * inv * g4.x + b4.x;
    o4.y = (v[1] - mu) * inv * g4.y + b4.y;
    o4.z = (v[2] - mu) * inv * g4.z + b4.z;
    o4.w = (v[3] - mu) * inv * g4.w + b4.w;
    *(float4*)(out + base + c) = o4;
}

// ===================== launch =====================
extern "C" void kernel_launch(void* const* d_in, const int* in_sizes, int n_in,
                              void* d_out, int out_size)
{
    const float* hidden = (const float*)d_in[0];
    const void*  mask   = d_in[1];
    const float* W[4]   = {(const float*)d_in[2], (const float*)d_in[3],
                           (const float*)d_in[4], (const float*)d_in[5]};
    const float* gamma  = (const float*)d_in[6];
    const float* beta   = (const float*)d_in[7];
    float* out = (float*)d_out;

    __half *phh, *pqkvh, *paoh, *pprojh, *pwh;
    cudaGetSymbolAddress((void**)&phh,    g_hh);
    cudaGetSymbolAddress((void**)&pqkvh,  g_qkvh);
    cudaGetSymbolAddress((void**)&paoh,   g_aoh);
    cudaGetSymbolAddress((void**)&pprojh, g_projh);
    cudaGetSymbolAddress((void**)&pwh,    g_wh);

    cudaFuncSetAttribute(gemm_fp16, cudaFuncAttributeMaxDynamicSharedMemorySize, GEMM_SMEM);
    cudaFuncSetAttribute(attn_hmma, cudaFuncAttributeMaxDynamicSharedMemorySize, ATTN_SMEM);

    detect_mask<<<1, 256>>>((const unsigned char*)mask);
    norm_mask<<<NROWS / 256, 256>>>(mask);

    conv_all<<<20480, 256>>>((const float4*)hidden,
        (const float4*)W[0], (const float4*)W[1], (const float4*)W[2], (const float4*)W[3],
        (uint2*)phh, (uint2*)pwh);

    dim3 gqkv(NQKV / 128, NROWS / 128);      // (24, 128) = 3072 CTAs
    gemm_fp16<<<gqkv, 256, GEMM_SMEM>>>(phh, pwh, pqkvh, NQKV);

    attn_hmma<<<NB * NH / 2, 256, ATTN_SMEM>>>();

    dim3 gout(DMODEL / 128, NROWS / 128);    // (8, 128)
    gemm_fp16<<<gout, 256, GEMM_SMEM>>>(paoh, pwh + 3 * (size_t)DMODEL * DMODEL, pprojh, DMODEL);

    resid_ln<<<NROWS, 256>>>(hidden, gamma, beta, out);
}

// round 12
// speedup vs baseline: 1.0984x; 1.0033x over previous
#include <cuda_runtime.h>
#include <cuda_fp16.h>
#include <cstdint>

#define NB      256
#define KS      64
#define DMODEL  1024
#define NQKV    3072
#define NH      16
#define DHEAD   64
#define NROWS   (NB*KS)          // 16384
#define SCALE   0.125f
#define LNEPS   1e-5f

#define SMEM_SWIZZLE_128B(o) ((o) ^ (((o) >> 3) & 0x70))

__device__ __forceinline__ uint32_t smem_to_u32(const void* p) {
    uint32_t a;
    asm("{ .reg .u64 t; cvta.to.shared.u64 t, %1; cvt.u32.u64 %0, t; }" : "=r"(a) : "l"(p));
    return a;
}
__device__ __forceinline__ void ldsm4(uint32_t* r, uint32_t addr) {
    asm volatile("ldmatrix.sync.aligned.m8n8.x4.shared.b16 {%0,%1,%2,%3}, [%4];"
        : "=r"(r[0]), "=r"(r[1]), "=r"(r[2]), "=r"(r[3]) : "r"(addr));
}
__device__ __forceinline__ void ldsm4t(uint32_t* r, uint32_t addr) {
    asm volatile("ldmatrix.sync.aligned.m8n8.x4.trans.shared.b16 {%0,%1,%2,%3}, [%4];"
        : "=r"(r[0]), "=r"(r[1]), "=r"(r[2]), "=r"(r[3]) : "r"(addr));
}
__device__ __forceinline__ void mma_fp16(float* c, const uint32_t* a, const uint32_t* b) {
    asm volatile("mma.sync.aligned.m16n8k16.row.col.f32.f16.f16.f32 "
        "{%0,%1,%2,%3}, {%4,%5,%6,%7}, {%8,%9}, {%0,%1,%2,%3};"
        : "+f"(c[0]), "+f"(c[1]), "+f"(c[2]), "+f"(c[3])
        : "r"(a[0]), "r"(a[1]), "r"(a[2]), "r"(a[3]), "r"(b[0]), "r"(b[1]));
}
#define CP_ASYNC16(dst, src) \
    asm volatile("cp.async.cg.shared.global [%0], [%1], 16;" :: "r"(dst), "l"(src))
#define CP_COMMIT() asm volatile("cp.async.commit_group;" ::: "memory")
#define CP_WAIT(n)  asm volatile("cp.async.wait_group %0;" :: "n"(n) : "memory")

// ===================== scratch =====================
__device__ float  g_mask[NROWS];
__device__ int    g_masktype;
__device__ __half g_hh[NROWS*DMODEL];
__device__ __half g_qkvh[NROWS*NQKV];
__device__ __half g_aoh[NROWS*DMODEL];
__device__ __half g_projh[NROWS*DMODEL];
__device__ __half g_wh[4*DMODEL*DMODEL];

// ===================== mask handling =====================
__global__ void detect_mask(const unsigned char* __restrict__ p) {
    __shared__ int sflt, smis;
    if (threadIdx.x == 0) { sflt = 0; smis = 0; }
    __syncthreads();
    int f = 0, ms = 0;
    for (int i = threadIdx.x; i < NROWS; i += 256) {
        unsigned char v = p[i];
        if (v > 1) f = 1;
        if (v != 0 && (i & 3)) ms = 1;
    }
    if (f)  atomicOr(&sflt, 1);
    if (ms) atomicOr(&smis, 1);
    __syncthreads();
    if (threadIdx.x == 0) g_masktype = sflt ? 0 : (smis ? 1 : 2);
}

__global__ void norm_mask(const void* __restrict__ p) {
    int i = blockIdx.x * blockDim.x + threadIdx.x;
    if (i >= NROWS) return;
    int t = g_masktype;
    float m;
    if (t == 0)      m = (((const float*)p)[i] != 0.0f) ? 1.0f : 0.0f;
    else if (t == 1) m = (((const unsigned char*)p)[i] != 0) ? 1.0f : 0.0f;
    else             m = (((const int*)p)[i] != 0) ? 1.0f : 0.0f;
    g_mask[i] = m;
}

// ===================== merged fp32 -> fp16 convert =====================
__global__ __launch_bounds__(256) void conv_all(
    const float4* __restrict__ hidden,
    const float4* __restrict__ w0, const float4* __restrict__ w1,
    const float4* __restrict__ w2, const float4* __restrict__ w3,
    uint2* __restrict__ dh, uint2* __restrict__ dw)
{
    const int bid = blockIdx.x;
    const float4* src;
    uint2* dst;
    int i;
    if (bid < 16384) {
        i = bid * 256 + threadIdx.x;
        src = hidden; dst = dh;
    } else {
        const int t = bid - 16384;
        const int w = t >> 10;
        src = (w == 0) ? w0 : (w == 1) ? w1 : (w == 2) ? w2 : w3;
        dst = dw + (size_t)w * (DMODEL * DMODEL / 4);
        i = (t & 1023) * 256 + threadIdx.x;
    }
    float4 v = src[i];
    __half2 a = __floats2half2_rn(v.x, v.y);
    __half2 b = __floats2half2_rn(v.z, v.w);
    uint2 u;
    u.x = *(uint32_t*)&a; u.y = *(uint32_t*)&b;
    dst[i] = u;
}

// ===================== fp16 HMMA GEMM: C = A @ B^T, fp16 out ================
#define STAGE_BYTES 32768
#define GSTAGES 3
#define GEMM_SMEM (GSTAGES * STAGE_BYTES)
#define NKT 16

__device__ __forceinline__ void load_stage_async(
    uint32_t sbase,
    const __half* __restrict__ A, const __half* __restrict__ B,
    int m0, int n0, int k0, int tid)
{
#pragma unroll
    for (int i = 0; i < 8; i++) {
        const int idx = tid + i * 256;
        const int buf = idx >> 10;
        const int j = idx & 1023;
        const int r = j >> 3, cc = j & 7;
        uint32_t so = sbase + buf * 16384 + SMEM_SWIZZLE_128B((uint32_t)(r * 128 + cc * 16));
        const __half* src = (buf == 0)
            ? A + (size_t)(m0 + r) * DMODEL + k0 + cc * 8
            : B + (size_t)(n0 + r) * DMODEL + k0 + cc * 8;
        CP_ASYNC16(so, src);
    }
}

__global__ __launch_bounds__(256, 2) void gemm_fp16(
    const __half* __restrict__ A, const __half* __restrict__ B,
    __half* __restrict__ C, int ldC)
{
    extern __shared__ char sm[];
    const uint32_t smem_base = smem_to_u32(sm);
    const int tid  = threadIdx.x;
    const int lane = tid & 31;
    const int wid  = tid >> 5;
    const int warp_m = wid & 1;
    const int warp_n = wid >> 1;
    const int m0 = blockIdx.y * 128;
    const int n0 = blockIdx.x * 128;
    const int m0w = warp_m * 64, n0w = warp_n * 32;

    float c[4][4][4];
#pragma unroll
    for (int mi = 0; mi < 4; mi++)
#pragma unroll
        for (int ni = 0; ni < 4; ni++)
#pragma unroll
            for (int e = 0; e < 4; e++) c[mi][ni][e] = 0.0f;

    load_stage_async(smem_base + 0 * STAGE_BYTES, A, B, m0, n0, 0, tid);
    CP_COMMIT();
    load_stage_async(smem_base + 1 * STAGE_BYTES, A, B, m0, n0, 64, tid);
    CP_COMMIT();

    const int arow  = m0w + (lane & 15);
    const int abyt  = ((lane >> 4) & 1) * 16;
    const int brow0 = n0w + ((lane >> 4) & 1) * 8 + (lane & 7);
    const int bbyt  = ((lane >> 3) & 1) * 16;

    int cur = 0;
    for (int kt = 0; kt < NKT; kt++) {
        CP_WAIT(1);
        __syncthreads();

        const uint32_t sb = smem_base + cur * STAGE_BYTES;

        // ks = 0 first: get tensor pipe busy before issuing next-stage loads
        {
            uint32_t af[4][4];
#pragma unroll
            for (int mi = 0; mi < 4; mi++)
                ldsm4(af[mi], sb + SMEM_SWIZZLE_128B((uint32_t)((arow + mi * 16) * 128 + abyt)));
            uint32_t bf[2][4];
#pragma unroll
            for (int g = 0; g < 2; g++)
                ldsm4(bf[g], sb + 16384 + SMEM_SWIZZLE_128B((uint32_t)((brow0 + g * 16) * 128 + bbyt)));
#pragma unroll
            for (int mi = 0; mi < 4; mi++)
#pragma unroll
                for (int ni = 0; ni < 4; ni++)
                    mma_fp16(c[mi][ni], af[mi], &bf[ni >> 1][(ni & 1) * 2]);
        }

        // prefetch stage kt+2 (targets (kt-1)%3, fully consumed before the
        // barrier above) while MMAs drain
        if (kt + 2 < NKT) {
            const int nxt = (kt + 2) % GSTAGES;
            load_stage_async(smem_base + nxt * STAGE_BYTES, A, B, m0, n0, (kt + 2) * 64, tid);
        }
        CP_COMMIT();

#pragma unroll
        for (int ks = 1; ks < 4; ks++) {
            uint32_t af[4][4];
#pragma unroll
            for (int mi = 0; mi < 4; mi++) {
                uint32_t off = SMEM_SWIZZLE_128B((uint32_t)((arow + mi * 16) * 128 + ks * 32 + abyt));
                ldsm4(af[mi], sb + off);
            }
            uint32_t bf[2][4];
#pragma unroll
            for (int g = 0; g < 2; g++) {
                uint32_t off = SMEM_SWIZZLE_128B((uint32_t)((brow0 + g * 16) * 128 + ks * 32 + bbyt));
                ldsm4(bf[g], sb + 16384 + off);
            }
#pragma unroll
            for (int mi = 0; mi < 4; mi++)
#pragma unroll
                for (int ni = 0; ni < 4; ni++)
                    mma_fp16(c[mi][ni], af[mi], &bf[ni >> 1][(ni & 1) * 2]);
        }
        cur = (cur + 1) % GSTAGES;
    }

#pragma unroll
    for (int mi = 0; mi < 4; mi++) {
        const int r0 = m0 + m0w + mi * 16 + (lane >> 2);
#pragma unroll
        for (int ni = 0; ni < 4; ni++) {
            const int cc = n0 + n0w + ni * 8 + (lane & 3) * 2;
            __half2 p0 = __floats2half2_rn(c[mi][ni][0], c[mi][ni][1]);
            __half2 p1 = __floats2half2_rn(c[mi][ni][2], c[mi][ni][3]);
            *(__half2*)(C + (size_t)r0 * ldC + cc)       = p0;
            *(__half2*)(C + (size_t)(r0 + 8) * ldC + cc) = p1;
        }
    }
}

// ===================== HMMA attention: 2 heads per CTA (256 thr) ============
#define ATTN_SMEM (8 * 8192)     // Q,K,V,S x 2 heads x 8KB

__global__ __launch_bounds__(256) void attn_hmma() {
    extern __shared__ char asm_[];
    const int bh2  = blockIdx.x;       // 0..2047
    const int b    = bh2 >> 3;
    const int h0   = (bh2 & 7) * 2;
    const int tid  = threadIdx.x;
    const int lane = tid & 31;
    const int wid  = tid >> 5;
    const int wh   = wid >> 2;         // head select
    const int wl   = wid & 3;          // warp within head

    char* const s_p = asm_ + 49152 + wh * 8192;
    const uint32_t base_s = smem_to_u32(asm_);
    const uint32_t q_s = base_s + wh * 8192;
    const uint32_t k_s = base_s + 16384 + wh * 8192;
    const uint32_t v_s = base_s + 32768 + wh * 8192;
    const uint32_t s_s = base_s + 49152 + wh * 8192;

    // cp.async loads for Q,K,V (both heads); 256B contiguous per row
    const size_t qbase = (size_t)(b * KS) * NQKV + h0 * DHEAD;
#pragma unroll
    for (int i = 0; i < 4; i++) {
        int idx = tid + i * 256;           // 0..1023 chunks (64 rows x 16)
        int r = idx >> 4, c16 = idx & 15;
        int hd = c16 >> 3, ch = c16 & 7;
        size_t ga = qbase + (size_t)r * NQKV + c16 * 8;
        uint32_t so = hd * 8192 + SMEM_SWIZZLE_128B((uint32_t)(r * 128 + ch * 16));
        CP_ASYNC16(base_s + so,          &g_qkvh[ga]);
        CP_ASYNC16(base_s + 16384 + so,  &g_qkvh[ga + 1024]);
        CP_ASYNC16(base_s + 32768 + so,  &g_qkvh[ga + 2048]);
    }
    CP_COMMIT();
    CP_WAIT(0);
    __syncthreads();

    // ---- S = Q @ K^T ----
    float c[8][4];
#pragma unroll
    for (int nb = 0; nb < 8; nb++)
#pragma unroll
        for (int e = 0; e < 4; e++) c[nb][e] = 0.0f;

    const int arow = wl * 16 + (lane & 15);
    const int abyt = ((lane >> 4) & 1) * 16;
    const int brow = ((lane >> 4) & 1) * 8 + (lane & 7);
    const int bbyt = ((lane >> 3) & 1) * 16;

#pragma unroll
    for (int ks = 0; ks < 4; ks++) {
        uint32_t af[4];
        ldsm4(af, q_s + SMEM_SWIZZLE_128B((uint32_t)(arow * 128 + ks * 32 + abyt)));
        uint32_t bf[4][4];
#pragma unroll
        for (int p = 0; p < 4; p++)
            ldsm4(bf[p], k_s + SMEM_SWIZZLE_128B((uint32_t)((p * 16 + brow) * 128 + ks * 32 + bbyt)));
#pragma unroll
        for (int nb = 0; nb < 8; nb++)
            mma_fp16(c[nb], af, &bf[nb >> 1][(nb & 1) * 2]);
    }

    // ---- softmax + mask ----
    const int r0 = wl * 16 + (lane >> 2);
    const int r1 = r0 + 8;
    float m0 = -1e30f, m1 = -1e30f;
#pragma unroll
    for (int nb = 0; nb < 8; nb++) {
#pragma unroll
        for (int e = 0; e < 4; e++) c[nb][e] *= SCALE;
        m0 = fmaxf(m0, fmaxf(c[nb][0], c[nb][1]));
        m1 = fmaxf(m1, fmaxf(c[nb][2], c[nb][3]));
    }
    m0 = fmaxf(m0, __shfl_xor_sync(0xffffffffu, m0, 1));
    m0 = fmaxf(m0, __shfl_xor_sync(0xffffffffu, m0, 2));
    m1 = fmaxf(m1, __shfl_xor_sync(0xffffffffu, m1, 1));
    m1 = fmaxf(m1, __shfl_xor_sync(0xffffffffu, m1, 2));
    float s0 = 0.0f, s1 = 0.0f;
#pragma unroll
    for (int nb = 0; nb < 8; nb++) {
        c[nb][0] = __expf(c[nb][0] - m0); s0 += c[nb][0];
        c[nb][1] = __expf(c[nb][1] - m0); s0 += c[nb][1];
        c[nb][2] = __expf(c[nb][2] - m1); s1 += c[nb][2];
        c[nb][3] = __expf(c[nb][3] - m1); s1 += c[nb][3];
    }
    s0 += __shfl_xor_sync(0xffffffffu, s0, 1);
    s0 += __shfl_xor_sync(0xffffffffu, s0, 2);
    s1 += __shfl_xor_sync(0xffffffffu, s1, 1);
    s1 += __shfl_xor_sync(0xffffffffu, s1, 2);
    const float w0 = g_mask[b * KS + r0] / s0;
    const float w1 = g_mask[b * KS + r1] / s1;

    const int scol = (lane & 3) * 2;
#pragma unroll
    for (int nb = 0; nb < 8; nb++) {
        __half2 p0 = __floats2half2_rn(c[nb][0] * w0, c[nb][1] * w0);
        __half2 p1 = __floats2half2_rn(c[nb][2] * w1, c[nb][3] * w1);
        *(__half2*)(s_p + SMEM_SWIZZLE_128B((uint32_t)(r0 * 128 + (nb * 8 + scol) * 2))) = p0;
        *(__half2*)(s_p + SMEM_SWIZZLE_128B((uint32_t)(r1 * 128 + (nb * 8 + scol) * 2))) = p1;
    }
    __syncwarp();

    // ---- O = S @ V ----
    float o[8][4];
#pragma unroll
    for (int nb = 0; nb < 8; nb++)
#pragma unroll
        for (int e = 0; e < 4; e++) o[nb][e] = 0.0f;

    const int g  = lane >> 3;
    const int gr = lane & 7;
#pragma unroll
    for (int ks = 0; ks < 4; ks++) {
        uint32_t af[4];
        ldsm4(af, s_s + SMEM_SWIZZLE_128B((uint32_t)(arow * 128 + ks * 32 + abyt)));
#pragma unroll
        for (int np = 0; np < 4; np++) {
            uint32_t bf[4];
            const int krow = ks * 16 + (g & 1) * 8 + gr;
            const int dcol = np * 16 + (g >> 1) * 8;
            ldsm4t(bf, v_s + SMEM_SWIZZLE_128B((uint32_t)(krow * 128 + dcol * 2)));
            mma_fp16(o[np * 2 + 0], af, &bf[0]);
            mma_fp16(o[np * 2 + 1], af, &bf[2]);
        }
    }

    const int h = h0 + wh;
    const size_t obase = (size_t)(b * KS) * DMODEL + h * DHEAD;
#pragma unroll
    for (int nb = 0; nb < 8; nb++) {
        __half2 p0 = __floats2half2_rn(o[nb][0], o[nb][1]);
        __half2 p1 = __floats2half2_rn(o[nb][2], o[nb][3]);
        *(__half2*)&g_aoh[obase + (size_t)r0 * DMODEL + nb * 8 + scol] = p0;
        *(__half2*)&g_aoh[obase + (size_t)r1 * DMODEL + nb * 8 + scol] = p1;
    }
}

// ===================== gated residual + LayerNorm ============
__global__ __launch_bounds__(256) void resid_ln(
    const float* __restrict__ hidden, const float* __restrict__ gamma,
    const float* __restrict__ beta, float* __restrict__ out)
{
    __shared__ float red[2][8];
    const int r = blockIdx.x;
    const float m = g_mask[r];
    const int c = threadIdx.x * 4;
    const size_t base = (size_t)r * DMODEL;

    float4 hv = *(const float4*)(hidden + base + c);
    uint2 pu = *(const uint2*)(&g_projh[base + c]);
    __half2 ph0 = *(__half2*)&pu.x;
    __half2 ph1 = *(__half2*)&pu.y;
    float2 pf0 = __half22float2(ph0);
    float2 pf1 = __half22float2(ph1);
    float v[4] = {hv.x + m * pf0.x, hv.y + m * pf0.y,
                  hv.z + m * pf1.x, hv.w + m * pf1.y};

    float s  = v[0] + v[1] + v[2] + v[3];
    float sq = v[0]*v[0] + v[1]*v[1] + v[2]*v[2] + v[3]*v[3];
#pragma unroll
    for (int o = 16; o; o >>= 1) {
        s  += __shfl_xor_sync(0xffffffffu, s, o);
        sq += __shfl_xor_sync(0xffffffffu, sq, o);
    }
    const int wid = threadIdx.x >> 5, lid = threadIdx.x & 31;
    if (lid == 0) { red[0][wid] = s; red[1][wid] = sq; }
    __syncthreads();
    s = 0.0f; sq = 0.0f;
#pragma unroll
    for (int i = 0; i < 8; i++) { s += red[0][i]; sq += red[1][i]; }

    const float mu  = s  * (1.0f / DMODEL);
    const float var = sq * (1.0f / DMODEL) - mu * mu;
    const float inv = rsqrtf(var + LNEPS);

    float4 g4 = *(const float4*)(gamma + c);
    float4 b4 = *(const float4*)(beta + c);
    float4 o4;
    o4.x = (v[0] - mu) * inv * g4.x + b4.x;
    o4.y = (v[1] - mu) * inv * g4.y + b4.y;
    o4.z = (v[2] - mu) * inv * g4.z + b4.z;
    o4.w = (v[3] - mu) * inv * g4.w + b4.w;
    *(float4*)(out + base + c) = o4;
}

// ===================== launch =====================
extern "C" void kernel_launch(void* const* d_in, const int* in_sizes, int n_in,
                              void* d_out, int out_size)
{
    const float* hidden = (const float*)d_in[0];
    const void*  mask   = d_in[1];
    const float* W[4]   = {(const float*)d_in[2], (const float*)d_in[3],
                           (const float*)d_in[4], (const float*)d_in[5]};
    const float* gamma  = (const float*)d_in[6];
    const float* beta   = (const float*)d_in[7];
    float* out = (float*)d_out;

    __half *phh, *pqkvh, *paoh, *pprojh, *pwh;
    cudaGetSymbolAddress((void**)&phh,    g_hh);
    cudaGetSymbolAddress((void**)&pqkvh,  g_qkvh);
    cudaGetSymbolAddress((void**)&paoh,   g_aoh);
    cudaGetSymbolAddress((void**)&pprojh, g_projh);
    cudaGetSymbolAddress((void**)&pwh,    g_wh);

    cudaFuncSetAttribute(gemm_fp16, cudaFuncAttributeMaxDynamicSharedMemorySize, GEMM_SMEM);
    cudaFuncSetAttribute(attn_hmma, cudaFuncAttributeMaxDynamicSharedMemorySize, ATTN_SMEM);

    detect_mask<<<1, 256>>>((const unsigned char*)mask);
    norm_mask<<<NROWS / 256, 256>>>(mask);

    conv_all<<<20480, 256>>>((const float4*)hidden,
        (const float4*)W[0], (const float4*)W[1], (const float4*)W[2], (const float4*)W[3],
        (uint2*)phh, (uint2*)pwh);

    dim3 gqkv(NQKV / 128, NROWS / 128);      // (24, 128) = 3072 CTAs
    gemm_fp16<<<gqkv, 256, GEMM_SMEM>>>(phh, pwh, pqkvh, NQKV);

    attn_hmma<<<NB * NH / 2, 256, ATTN_SMEM>>>();

    dim3 gout(DMODEL / 128, NROWS / 128);    // (8, 128)
    gemm_fp16<<<gout, 256, GEMM_SMEM>>>(paoh, pwh + 3 * (size_t)DMODEL * DMODEL, pprojh, DMODEL);

    resid_ln<<<NROWS, 256>>>(hidden, gamma, beta, out);
}

// round 14
// speedup vs baseline: 1.1270x; 1.0261x over previous
#include <cuda_runtime.h>
#include <cuda_fp16.h>
#include <cstdint>

#define NB      256
#define KS      64
#define DMODEL  1024
#define NQKV    3072
#define NH      16
#define DHEAD   64
#define NROWS   (NB*KS)          // 16384
#define SCALE   0.125f
#define LNEPS   1e-5f

#define SMEM_SWIZZLE_128B(o) ((o) ^ (((o) >> 3) & 0x70))

__device__ __forceinline__ uint32_t smem_to_u32(const void* p) {
    uint32_t a;
    asm("{ .reg .u64 t; cvta.to.shared.u64 t, %1; cvt.u32.u64 %0, t; }" : "=r"(a) : "l"(p));
    return a;
}
__device__ __forceinline__ void ldsm4(uint32_t* r, uint32_t addr) {
    asm volatile("ldmatrix.sync.aligned.m8n8.x4.shared.b16 {%0,%1,%2,%3}, [%4];"
        : "=r"(r[0]), "=r"(r[1]), "=r"(r[2]), "=r"(r[3]) : "r"(addr));
}
__device__ __forceinline__ void ldsm4t(uint32_t* r, uint32_t addr) {
    asm volatile("ldmatrix.sync.aligned.m8n8.x4.trans.shared.b16 {%0,%1,%2,%3}, [%4];"
        : "=r"(r[0]), "=r"(r[1]), "=r"(r[2]), "=r"(r[3]) : "r"(addr));
}
__device__ __forceinline__ void mma_fp16(float* c, const uint32_t* a, const uint32_t* b) {
    asm volatile("mma.sync.aligned.m16n8k16.row.col.f32.f16.f16.f32 "
        "{%0,%1,%2,%3}, {%4,%5,%6,%7}, {%8,%9}, {%0,%1,%2,%3};"
        : "+f"(c[0]), "+f"(c[1]), "+f"(c[2]), "+f"(c[3])
        : "r"(a[0]), "r"(a[1]), "r"(a[2]), "r"(a[3]), "r"(b[0]), "r"(b[1]));
}
#define CP_ASYNC16(dst, src) \
    asm volatile("cp.async.cg.shared.global [%0], [%1], 16;" :: "r"(dst), "l"(src))
#define CP_COMMIT() asm volatile("cp.async.commit_group;" ::: "memory")
#define CP_WAIT(n)  asm volatile("cp.async.wait_group %0;" :: "n"(n) : "memory")

// ===================== scratch =====================
__device__ float  g_mask[NROWS];
__device__ int    g_masktype;
__device__ __half g_hh[NROWS*DMODEL];
__device__ __half g_qkvh[NROWS*NQKV];
__device__ __half g_aoh[NROWS*DMODEL];
__device__ __half g_projh[NROWS*DMODEL];
__device__ __half g_wh[4*DMODEL*DMODEL];

// ===================== mask handling =====================
__global__ void detect_mask(const unsigned char* __restrict__ p) {
    __shared__ int sflt, smis;
    if (threadIdx.x == 0) { sflt = 0; smis = 0; }
    __syncthreads();
    int f = 0, ms = 0;
    for (int i = threadIdx.x; i < NROWS; i += 256) {
        unsigned char v = p[i];
        if (v > 1) f = 1;
        if (v != 0 && (i & 3)) ms = 1;
    }
    if (f)  atomicOr(&sflt, 1);
    if (ms) atomicOr(&smis, 1);
    __syncthreads();
    if (threadIdx.x == 0) g_masktype = sflt ? 0 : (smis ? 1 : 2);
}

__global__ void norm_mask(const void* __restrict__ p) {
    int i = blockIdx.x * blockDim.x + threadIdx.x;
    if (i >= NROWS) return;
    int t = g_masktype;
    float m;
    if (t == 0)      m = (((const float*)p)[i] != 0.0f) ? 1.0f : 0.0f;
    else if (t == 1) m = (((const unsigned char*)p)[i] != 0) ? 1.0f : 0.0f;
    else             m = (((const int*)p)[i] != 0) ? 1.0f : 0.0f;
    g_mask[i] = m;
}

// ===================== merged fp32 -> fp16 convert =====================
__global__ __launch_bounds__(256) void conv_all(
    const float4* __restrict__ hidden,
    const float4* __restrict__ w0, const float4* __restrict__ w1,
    const float4* __restrict__ w2, const float4* __restrict__ w3,
    uint2* __restrict__ dh, uint2* __restrict__ dw)
{
    const int bid = blockIdx.x;
    const float4* src;
    uint2* dst;
    int i;
    if (bid < 16384) {
        i = bid * 256 + threadIdx.x;
        src = hidden; dst = dh;
    } else {
        const int t = bid - 16384;
        const int w = t >> 10;
        src = (w == 0) ? w0 : (w == 1) ? w1 : (w == 2) ? w2 : w3;
        dst = dw + (size_t)w * (DMODEL * DMODEL / 4);
        i = (t & 1023) * 256 + threadIdx.x;
    }
    float4 v = src[i];
    __half2 a = __floats2half2_rn(v.x, v.y);
    __half2 b = __floats2half2_rn(v.z, v.w);
    uint2 u;
    u.x = *(uint32_t*)&a; u.y = *(uint32_t*)&b;
    dst[i] = u;
}

// ===================== fp16 HMMA GEMM: C = A @ B^T, fp16 out ================
// CTA tile 128x128, 4 warps (2x2), warp tile 64x64, K-tile 64, 3-stage,
// 2 CTAs/SM (96KB smem, 128 threads, <=256 regs).
#define STAGE_BYTES 32768
#define GSTAGES 3
#define GEMM_SMEM (GSTAGES * STAGE_BYTES)
#define NKT 16

__device__ __forceinline__ void load_stage_async(
    uint32_t sbase,
    const __half* __restrict__ A, const __half* __restrict__ B,
    int m0, int n0, int k0, int tid)
{
#pragma unroll
    for (int i = 0; i < 16; i++) {
        const int idx = tid + i * 128;           // 0..2047 16B chunks
        const int buf = idx >> 10;               // 0:A 1:B
        const int j = idx & 1023;
        const int r = j >> 3, cc = j & 7;
        uint32_t so = sbase + buf * 16384 + SMEM_SWIZZLE_128B((uint32_t)(r * 128 + cc * 16));
        const __half* src = (buf == 0)
            ? A + (size_t)(m0 + r) * DMODEL + k0 + cc * 8
            : B + (size_t)(n0 + r) * DMODEL + k0 + cc * 8;
        CP_ASYNC16(so, src);
    }
}

__global__ __launch_bounds__(128, 2) void gemm_fp16(
    const __half* __restrict__ A, const __half* __restrict__ B,
    __half* __restrict__ C, int ldC)
{
    extern __shared__ char sm[];
    const uint32_t smem_base = smem_to_u32(sm);
    const int tid  = threadIdx.x;
    const int lane = tid & 31;
    const int wid  = tid >> 5;       // 0..3
    const int warp_m = wid & 1;      // 2 warps in M
    const int warp_n = wid >> 1;     // 2 warps in N
    const int m0 = blockIdx.y * 128;
    const int n0 = blockIdx.x * 128;
    const int m0w = warp_m * 64, n0w = warp_n * 64;

    float c[4][8][4];
#pragma unroll
    for (int mi = 0; mi < 4; mi++)
#pragma unroll
        for (int ni = 0; ni < 8; ni++)
#pragma unroll
            for (int e = 0; e < 4; e++) c[mi][ni][e] = 0.0f;

    load_stage_async(smem_base + 0 * STAGE_BYTES, A, B, m0, n0, 0, tid);
    CP_COMMIT();
    load_stage_async(smem_base + 1 * STAGE_BYTES, A, B, m0, n0, 64, tid);
    CP_COMMIT();

    const int arow = m0w + (lane & 15);
    const int abyt = ((lane >> 4) & 1) * 16;
    const int brow = ((lane >> 4) & 1) * 8 + (lane & 7);
    const int bbyt = ((lane >> 3) & 1) * 16;

    int cur = 0;
    for (int kt = 0; kt < NKT; kt++) {
        CP_WAIT(1);
        __syncthreads();

        const uint32_t sb = smem_base + cur * STAGE_BYTES;

        // ks = 0 first, then issue next-stage prefetch while MMAs drain.
        // Prefetch targets stage (kt+2)%3 == (kt-1)%3, fully consumed before
        // the barrier above — no tail barrier needed.
        {
            uint32_t af[4][4];
#pragma unroll
            for (int mi = 0; mi < 4; mi++)
                ldsm4(af[mi], sb + SMEM_SWIZZLE_128B((uint32_t)((arow + mi * 16) * 128 + abyt)));
            uint32_t bf[4][4];
#pragma unroll
            for (int p = 0; p < 4; p++)
                ldsm4(bf[p], sb + 16384 + SMEM_SWIZZLE_128B((uint32_t)((n0w + p * 16 + brow) * 128 + bbyt)));
#pragma unroll
            for (int mi = 0; mi < 4; mi++)
#pragma unroll
                for (int ni = 0; ni < 8; ni++)
                    mma_fp16(c[mi][ni], af[mi], &bf[ni >> 1][(ni & 1) * 2]);
        }

        if (kt + 2 < NKT) {
            const int nxt = (kt + 2) % GSTAGES;
            load_stage_async(smem_base + nxt * STAGE_BYTES, A, B, m0, n0, (kt + 2) * 64, tid);
        }
        CP_COMMIT();

#pragma unroll
        for (int ks = 1; ks < 4; ks++) {
            uint32_t af[4][4];
#pragma unroll
            for (int mi = 0; mi < 4; mi++) {
                uint32_t off = SMEM_SWIZZLE_128B((uint32_t)((arow + mi * 16) * 128 + ks * 32 + abyt));
                ldsm4(af[mi], sb + off);
            }
            uint32_t bf[4][4];
#pragma unroll
            for (int p = 0; p < 4; p++) {
                uint32_t off = SMEM_SWIZZLE_128B((uint32_t)((n0w + p * 16 + brow) * 128 + ks * 32 + bbyt));
                ldsm4(bf[p], sb + 16384 + off);
            }
#pragma unroll
            for (int mi = 0; mi < 4; mi++)
#pragma unroll
                for (int ni = 0; ni < 8; ni++)
                    mma_fp16(c[mi][ni], af[mi], &bf[ni >> 1][(ni & 1) * 2]);
        }
        cur = (cur + 1) % GSTAGES;
    }

#pragma unroll
    for (int mi = 0; mi < 4; mi++) {
        const int r0 = m0 + m0w + mi * 16 + (lane >> 2);
#pragma unroll
        for (int ni = 0; ni < 8; ni++) {
            const int cc = n0 + n0w + ni * 8 + (lane & 3) * 2;
            __half2 p0 = __floats2half2_rn(c[mi][ni][0], c[mi][ni][1]);
            __half2 p1 = __floats2half2_rn(c[mi][ni][2], c[mi][ni][3]);
            *(__half2*)(C + (size_t)r0 * ldC + cc)       = p0;
            *(__half2*)(C + (size_t)(r0 + 8) * ldC + cc) = p1;
        }
    }
}

// ===================== HMMA attention: 2 heads per CTA (256 thr) ============
#define ATTN_SMEM (8 * 8192)     // Q,K,V,S x 2 heads x 8KB

__global__ __launch_bounds__(256) void attn_hmma() {
    extern __shared__ char asm_[];
    const int bh2  = blockIdx.x;       // 0..2047
    const int b    = bh2 >> 3;
    const int h0   = (bh2 & 7) * 2;
    const int tid  = threadIdx.x;
    const int lane = tid & 31;
    const int wid  = tid >> 5;
    const int wh   = wid >> 2;         // head select
    const int wl   = wid & 3;          // warp within head

    char* const s_p = asm_ + 49152 + wh * 8192;
    const uint32_t base_s = smem_to_u32(asm_);
    const uint32_t q_s = base_s + wh * 8192;
    const uint32_t k_s = base_s + 16384 + wh * 8192;
    const uint32_t v_s = base_s + 32768 + wh * 8192;
    const uint32_t s_s = base_s + 49152 + wh * 8192;

    const size_t qbase = (size_t)(b * KS) * NQKV + h0 * DHEAD;
#pragma unroll
    for (int i = 0; i < 4; i++) {
        int idx = tid + i * 256;           // 0..1023 chunks (64 rows x 16)
        int r = idx >> 4, c16 = idx & 15;
        int hd = c16 >> 3, ch = c16 & 7;
        size_t ga = qbase + (size_t)r * NQKV + c16 * 8;
        uint32_t so = hd * 8192 + SMEM_SWIZZLE_128B((uint32_t)(r * 128 + ch * 16));
        CP_ASYNC16(base_s + so,          &g_qkvh[ga]);
        CP_ASYNC16(base_s + 16384 + so,  &g_qkvh[ga + 1024]);
        CP_ASYNC16(base_s + 32768 + so,  &g_qkvh[ga + 2048]);
    }
    CP_COMMIT();
    CP_WAIT(0);
    __syncthreads();

    // ---- S = Q @ K^T ----
    float c[8][4];
#pragma unroll
    for (int nb = 0; nb < 8; nb++)
#pragma unroll
        for (int e = 0; e < 4; e++) c[nb][e] = 0.0f;

    const int arow = wl * 16 + (lane & 15);
    const int abyt = ((lane >> 4) & 1) * 16;
    const int brow = ((lane >> 4) & 1) * 8 + (lane & 7);
    const int bbyt = ((lane >> 3) & 1) * 16;

#pragma unroll
    for (int ks = 0; ks < 4; ks++) {
        uint32_t af[4];
        ldsm4(af, q_s + SMEM_SWIZZLE_128B((uint32_t)(arow * 128 + ks * 32 + abyt)));
        uint32_t bf[4][4];
#pragma unroll
        for (int p = 0; p < 4; p++)
            ldsm4(bf[p], k_s + SMEM_SWIZZLE_128B((uint32_t)((p * 16 + brow) * 128 + ks * 32 + bbyt)));
#pragma unroll
        for (int nb = 0; nb < 8; nb++)
            mma_fp16(c[nb], af, &bf[nb >> 1][(nb & 1) * 2]);
    }

    // ---- softmax + mask ----
    const int r0 = wl * 16 + (lane >> 2);
    const int r1 = r0 + 8;
    float m0 = -1e30f, m1 = -1e30f;
#pragma unroll
    for (int nb = 0; nb < 8; nb++) {
#pragma unroll
        for (int e = 0; e < 4; e++) c[nb][e] *= SCALE;
        m0 = fmaxf(m0, fmaxf(c[nb][0], c[nb][1]));
        m1 = fmaxf(m1, fmaxf(c[nb][2], c[nb][3]));
    }
    m0 = fmaxf(m0, __shfl_xor_sync(0xffffffffu, m0, 1));
    m0 = fmaxf(m0, __shfl_xor_sync(0xffffffffu, m0, 2));
    m1 = fmaxf(m1, __shfl_xor_sync(0xffffffffu, m1, 1));
    m1 = fmaxf(m1, __shfl_xor_sync(0xffffffffu, m1, 2));
    float s0 = 0.0f, s1 = 0.0f;
#pragma unroll
    for (int nb = 0; nb < 8; nb++) {
        c[nb][0] = __expf(c[nb][0] - m0); s0 += c[nb][0];
        c[nb][1] = __expf(c[nb][1] - m0); s0 += c[nb][1];
        c[nb][2] = __expf(c[nb][2] - m1); s1 += c[nb][2];
        c[nb][3] = __expf(c[nb][3] - m1); s1 += c[nb][3];
    }
    s0 += __shfl_xor_sync(0xffffffffu, s0, 1);
    s0 += __shfl_xor_sync(0xffffffffu, s0, 2);
    s1 += __shfl_xor_sync(0xffffffffu, s1, 1);
    s1 += __shfl_xor_sync(0xffffffffu, s1, 2);
    const float w0 = g_mask[b * KS + r0] / s0;
    const float w1 = g_mask[b * KS + r1] / s1;

    const int scol = (lane & 3) * 2;
#pragma unroll
    for (int nb = 0; nb < 8; nb++) {
        __half2 p0 = __floats2half2_rn(c[nb][0] * w0, c[nb][1] * w0);
        __half2 p1 = __floats2half2_rn(c[nb][2] * w1, c[nb][3] * w1);
        *(__half2*)(s_p + SMEM_SWIZZLE_128B((uint32_t)(r0 * 128 + (nb * 8 + scol) * 2))) = p0;
        *(__half2*)(s_p + SMEM_SWIZZLE_128B((uint32_t)(r1 * 128 + (nb * 8 + scol) * 2))) = p1;
    }
    __syncwarp();

    // ---- O = S @ V ----
    float o[8][4];
#pragma unroll
    for (int nb = 0; nb < 8; nb++)
#pragma unroll
        for (int e = 0; e < 4; e++) o[nb][e] = 0.0f;

    const int g  = lane >> 3;
    const int gr = lane & 7;
#pragma unroll
    for (int ks = 0; ks < 4; ks++) {
        uint32_t af[4];
        ldsm4(af, s_s + SMEM_SWIZZLE_128B((uint32_t)(arow * 128 + ks * 32 + abyt)));
#pragma unroll
        for (int np = 0; np < 4; np++) {
            uint32_t bf[4];
            const int krow = ks * 16 + (g & 1) * 8 + gr;
            const int dcol = np * 16 + (g >> 1) * 8;
            ldsm4t(bf, v_s + SMEM_SWIZZLE_128B((uint32_t)(krow * 128 + dcol * 2)));
            mma_fp16(o[np * 2 + 0], af, &bf[0]);
            mma_fp16(o[np * 2 + 1], af, &bf[2]);
        }
    }

    const int h = h0 + wh;
    const size_t obase = (size_t)(b * KS) * DMODEL + h * DHEAD;
#pragma unroll
    for (int nb = 0; nb < 8; nb++) {
        __half2 p0 = __floats2half2_rn(o[nb][0], o[nb][1]);
        __half2 p1 = __floats2half2_rn(o[nb][2], o[nb][3]);
        *(__half2*)&g_aoh[obase + (size_t)r0 * DMODEL + nb * 8 + scol] = p0;
        *(__half2*)&g_aoh[obase + (size_t)r1 * DMODEL + nb * 8 + scol] = p1;
    }
}

// ===================== gated residual + LayerNorm ============
__global__ __launch_bounds__(256) void resid_ln(
    const float* __restrict__ hidden, const float* __restrict__ gamma,
    const float* __restrict__ beta, float* __restrict__ out)
{
    __shared__ float red[2][8];
    const int r = blockIdx.x;
    const float m = g_mask[r];
    const int c = threadIdx.x * 4;
    const size_t base = (size_t)r * DMODEL;

    float4 hv = *(const float4*)(hidden + base + c);
    uint2 pu = *(const uint2*)(&g_projh[base + c]);
    __half2 ph0 = *(__half2*)&pu.x;
    __half2 ph1 = *(__half2*)&pu.y;
    float2 pf0 = __half22float2(ph0);
    float2 pf1 = __half22float2(ph1);
    float v[4] = {hv.x + m * pf0.x, hv.y + m * pf0.y,
                  hv.z + m * pf1.x, hv.w + m * pf1.y};

    float s  = v[0] + v[1] + v[2] + v[3];
    float sq = v[0]*v[0] + v[1]*v[1] + v[2]*v[2] + v[3]*v[3];
#pragma unroll
    for (int o = 16; o; o >>= 1) {
        s  += __shfl_xor_sync(0xffffffffu, s, o);
        sq += __shfl_xor_sync(0xffffffffu, sq, o);
    }
    const int wid = threadIdx.x >> 5, lid = threadIdx.x & 31;
    if (lid == 0) { red[0][wid] = s; red[1][wid] = sq; }
    __syncthreads();
    s = 0.0f; sq = 0.0f;
#pragma unroll
    for (int i = 0; i < 8; i++) { s += red[0][i]; sq += red[1][i]; }

    const float mu  = s  * (1.0f / DMODEL);
    const float var = sq * (1.0f / DMODEL) - mu * mu;
    const float inv = rsqrtf(var + LNEPS);

    float4 g4 = *(const float4*)(gamma + c);
    float4 b4 = *(const float4*)(beta + c);
    float4 o4;
    o4.x = (v[0] - mu) * inv * g4.x + b4.x;
    o4.y = (v[1] - mu) * inv * g4.y + b4.y;
    o4.z = (v[2] - mu) * inv * g4.z + b4.z;
    o4.w = (v[3] - mu) * inv * g4.w + b4.w;
    *(float4*)(out + base + c) = o4;
}

// ===================== launch =====================
extern "C" void kernel_launch(void* const* d_in, const int* in_sizes, int n_in,
                              void* d_out, int out_size)
{
    const float* hidden = (const float*)d_in[0];
    const void*  mask   = d_in[1];
    const float* W[4]   = {(const float*)d_in[2], (const float*)d_in[3],
                           (const float*)d_in[4], (const float*)d_in[5]};
    const float* gamma  = (const float*)d_in[6];
    const float* beta   = (const float*)d_in[7];
    float* out = (float*)d_out;

    __half *phh, *pqkvh, *paoh, *pprojh, *pwh;
    cudaGetSymbolAddress((void**)&phh,    g_hh);
    cudaGetSymbolAddress((void**)&pqkvh,  g_qkvh);
    cudaGetSymbolAddress((void**)&paoh,   g_aoh);
    cudaGetSymbolAddress((void**)&pprojh, g_projh);
    cudaGetSymbolAddress((void**)&pwh,    g_wh);

    cudaFuncSetAttribute(gemm_fp16, cudaFuncAttributeMaxDynamicSharedMemorySize, GEMM_SMEM);
    cudaFuncSetAttribute(attn_hmma, cudaFuncAttributeMaxDynamicSharedMemorySize, ATTN_SMEM);

    detect_mask<<<1, 256>>>((const unsigned char*)mask);
    norm_mask<<<NROWS / 256, 256>>>(mask);

    conv_all<<<20480, 256>>>((const float4*)hidden,
        (const float4*)W[0], (const float4*)W[1], (const float4*)W[2], (const float4*)W[3],
        (uint2*)phh, (uint2*)pwh);

    dim3 gqkv(NQKV / 128, NROWS / 128);      // (24, 128) = 3072 CTAs
    gemm_fp16<<<gqkv, 128, GEMM_SMEM>>>(phh, pwh, pqkvh, NQKV);

    attn_hmma<<<NB * NH / 2, 256, ATTN_SMEM>>>();

    dim3 gout(DMODEL / 128, NROWS / 128);    // (8, 128)
    gemm_fp16<<<gout, 128, GEMM_SMEM>>>(paoh, pwh + 3 * (size_t)DMODEL * DMODEL, pprojh, DMODEL);

    resid_ln<<<NROWS, 256>>>(hidden, gamma, beta, out);
}

// round 15
// speedup vs baseline: 1.1370x; 1.0088x over previous
#include <cuda_runtime.h>
#include <cuda_fp16.h>
#include <cstdint>

#define NB      256
#define KS      64
#define DMODEL  1024
#define NQKV    3072
#define NH      16
#define DHEAD   64
#define NROWS   (NB*KS)          // 16384
#define SCALE   0.125f
#define LNEPS   1e-5f

#define SMEM_SWIZZLE_128B(o) ((o) ^ (((o) >> 3) & 0x70))

__device__ __forceinline__ uint32_t smem_to_u32(const void* p) {
    uint32_t a;
    asm("{ .reg .u64 t; cvta.to.shared.u64 t, %1; cvt.u32.u64 %0, t; }" : "=r"(a) : "l"(p));
    return a;
}
__device__ __forceinline__ void ldsm4(uint32_t* r, uint32_t addr) {
    asm volatile("ldmatrix.sync.aligned.m8n8.x4.shared.b16 {%0,%1,%2,%3}, [%4];"
        : "=r"(r[0]), "=r"(r[1]), "=r"(r[2]), "=r"(r[3]) : "r"(addr));
}
__device__ __forceinline__ void ldsm4t(uint32_t* r, uint32_t addr) {
    asm volatile("ldmatrix.sync.aligned.m8n8.x4.trans.shared.b16 {%0,%1,%2,%3}, [%4];"
        : "=r"(r[0]), "=r"(r[1]), "=r"(r[2]), "=r"(r[3]) : "r"(addr));
}
__device__ __forceinline__ void mma_fp16(float* c, const uint32_t* a, const uint32_t* b) {
    asm volatile("mma.sync.aligned.m16n8k16.row.col.f32.f16.f16.f32 "
        "{%0,%1,%2,%3}, {%4,%5,%6,%7}, {%8,%9}, {%0,%1,%2,%3};"
        : "+f"(c[0]), "+f"(c[1]), "+f"(c[2]), "+f"(c[3])
        : "r"(a[0]), "r"(a[1]), "r"(a[2]), "r"(a[3]), "r"(b[0]), "r"(b[1]));
}
#define CP_ASYNC16(dst, src) \
    asm volatile("cp.async.cg.shared.global [%0], [%1], 16;" :: "r"(dst), "l"(src))
#define CP_COMMIT() asm volatile("cp.async.commit_group;" ::: "memory")
#define CP_WAIT(n)  asm volatile("cp.async.wait_group %0;" :: "n"(n) : "memory")

// ===================== scratch =====================
__device__ float  g_mask[NROWS];
__device__ int    g_masktype;
__device__ __half g_hh[NROWS*DMODEL];
__device__ __half g_qkvh[NROWS*NQKV];
__device__ __half g_aoh[NROWS*DMODEL];
__device__ __half g_projh[NROWS*DMODEL];
__device__ __half g_wh[4*DMODEL*DMODEL];

// ===================== mask handling =====================
__global__ void detect_mask(const unsigned char* __restrict__ p) {
    __shared__ int sflt, smis;
    if (threadIdx.x == 0) { sflt = 0; smis = 0; }
    __syncthreads();
    int f = 0, ms = 0;
    for (int i = threadIdx.x; i < NROWS; i += 256) {
        unsigned char v = p[i];
        if (v > 1) f = 1;
        if (v != 0 && (i & 3)) ms = 1;
    }
    if (f)  atomicOr(&sflt, 1);
    if (ms) atomicOr(&smis, 1);
    __syncthreads();
    if (threadIdx.x == 0) g_masktype = sflt ? 0 : (smis ? 1 : 2);
}

__global__ void norm_mask(const void* __restrict__ p) {
    int i = blockIdx.x * blockDim.x + threadIdx.x;
    if (i >= NROWS) return;
    int t = g_masktype;
    float m;
    if (t == 0)      m = (((const float*)p)[i] != 0.0f) ? 1.0f : 0.0f;
    else if (t == 1) m = (((const unsigned char*)p)[i] != 0) ? 1.0f : 0.0f;
    else             m = (((const int*)p)[i] != 0) ? 1.0f : 0.0f;
    g_mask[i] = m;
}

// ===================== merged fp32 -> fp16 convert =====================
__global__ __launch_bounds__(256) void conv_all(
    const float4* __restrict__ hidden,
    const float4* __restrict__ w0, const float4* __restrict__ w1,
    const float4* __restrict__ w2, const float4* __restrict__ w3,
    uint2* __restrict__ dh, uint2* __restrict__ dw)
{
    const int bid = blockIdx.x;
    const float4* src;
    uint2* dst;
    int i;
    if (bid < 16384) {
        i = bid * 256 + threadIdx.x;
        src = hidden; dst = dh;
    } else {
        const int t = bid - 16384;
        const int w = t >> 10;
        src = (w == 0) ? w0 : (w == 1) ? w1 : (w == 2) ? w2 : w3;
        dst = dw + (size_t)w * (DMODEL * DMODEL / 4);
        i = (t & 1023) * 256 + threadIdx.x;
    }
    float4 v = src[i];
    __half2 a = __floats2half2_rn(v.x, v.y);
    __half2 b = __floats2half2_rn(v.z, v.w);
    uint2 u;
    u.x = *(uint32_t*)&a; u.y = *(uint32_t*)&b;
    dst[i] = u;
}

// ===================== persistent fp16 HMMA GEMM: C = A @ B^T ================
// CTA tile 128x128, 4 warps (2x2), warp tile 64x64, K-tile 64, 3-stage,
// 2 CTAs/SM, persistent tiles with cross-tile pipeline bridging.
#define STAGE_BYTES 32768
#define GSTAGES 3
#define GEMM_SMEM (GSTAGES * STAGE_BYTES)
#define NKT 16
#define GEMM_GRID 304            // 2 x 152 SMs

__device__ __forceinline__ void load_stage_async(
    uint32_t sbase,
    const __half* __restrict__ A, const __half* __restrict__ B,
    int m0, int n0, int k0, int tid)
{
#pragma unroll
    for (int i = 0; i < 16; i++) {
        const int idx = tid + i * 128;           // 0..2047 16B chunks
        const int buf = idx >> 10;               // 0:A 1:B
        const int j = idx & 1023;
        const int r = j >> 3, cc = j & 7;
        uint32_t so = sbase + buf * 16384 + SMEM_SWIZZLE_128B((uint32_t)(r * 128 + cc * 16));
        const __half* src = (buf == 0)
            ? A + (size_t)(m0 + r) * DMODEL + k0 + cc * 8
            : B + (size_t)(n0 + r) * DMODEL + k0 + cc * 8;
        CP_ASYNC16(so, src);
    }
}

__global__ __launch_bounds__(128, 2) void gemm_fp16(
    const __half* __restrict__ A, const __half* __restrict__ B,
    __half* __restrict__ C, int ldC)
{
    extern __shared__ char sm[];
    const uint32_t smem_base = smem_to_u32(sm);
    const int tid  = threadIdx.x;
    const int lane = tid & 31;
    const int wid  = tid >> 5;       // 0..3
    const int warp_m = wid & 1;
    const int warp_n = wid >> 1;
    const int m0w = warp_m * 64, n0w = warp_n * 64;

    const int ntn = ldC >> 7;                     // tiles along N
    const int ntotal = (NROWS >> 7) * ntn;

    int tile = blockIdx.x;
    if (tile >= ntotal) return;
    int m0 = (tile / ntn) << 7;
    int n0 = (tile % ntn) << 7;

    const int arow_l = (lane & 15);
    const int abyt = ((lane >> 4) & 1) * 16;
    const int brow = ((lane >> 4) & 1) * 8 + (lane & 7);
    const int bbyt = ((lane >> 3) & 1) * 16;

    float c[4][8][4];
#pragma unroll
    for (int mi = 0; mi < 4; mi++)
#pragma unroll
        for (int ni = 0; ni < 8; ni++)
#pragma unroll
            for (int e = 0; e < 4; e++) c[mi][ni][e] = 0.0f;

    load_stage_async(smem_base + 0 * STAGE_BYTES, A, B, m0, n0, 0, tid);
    CP_COMMIT();
    load_stage_async(smem_base + 1 * STAGE_BYTES, A, B, m0, n0, 64, tid);
    CP_COMMIT();

    int cur = 0;
    while (true) {
        const int next_tile = tile + GEMM_GRID;
        const bool has_next = next_tile < ntotal;
        int nm0 = 0, nn0 = 0;
        if (has_next) { nm0 = (next_tile / ntn) << 7; nn0 = (next_tile % ntn) << 7; }

        for (int kt = 0; kt < NKT; kt++) {
            CP_WAIT(1);
            __syncthreads();

            const uint32_t sb = smem_base + cur * STAGE_BYTES;

            // ks = 0 first: tensor pipe busy before issuing prefetch
            {
                uint32_t af[4][4];
#pragma unroll
                for (int mi = 0; mi < 4; mi++)
                    ldsm4(af[mi], sb + SMEM_SWIZZLE_128B((uint32_t)((m0w + mi * 16 + arow_l) * 128 + abyt)));
                uint32_t bf[4][4];
#pragma unroll
                for (int p = 0; p < 4; p++)
                    ldsm4(bf[p], sb + 16384 + SMEM_SWIZZLE_128B((uint32_t)((n0w + p * 16 + brow) * 128 + bbyt)));
#pragma unroll
                for (int mi = 0; mi < 4; mi++)
#pragma unroll
                    for (int ni = 0; ni < 8; ni++)
                        mma_fp16(c[mi][ni], af[mi], &bf[ni >> 1][(ni & 1) * 2]);
            }

            // prefetch 2 stages ahead; bridges into the next tile's k=0,64.
            // Target stage (cur+2)%3 was fully consumed 3 iterations ago.
            {
                const uint32_t lstage = smem_base + ((cur + 2) % GSTAGES) * STAGE_BYTES;
                if (kt + 2 < NKT)
                    load_stage_async(lstage, A, B, m0, n0, (kt + 2) * 64, tid);
                else if (has_next)
                    load_stage_async(lstage, A, B, nm0, nn0, (kt + 2 - NKT) * 64, tid);
            }
            CP_COMMIT();

#pragma unroll
            for (int ks = 1; ks < 4; ks++) {
                uint32_t af[4][4];
#pragma unroll
                for (int mi = 0; mi < 4; mi++) {
                    uint32_t off = SMEM_SWIZZLE_128B((uint32_t)((m0w + mi * 16 + arow_l) * 128 + ks * 32 + abyt));
                    ldsm4(af[mi], sb + off);
                }
                uint32_t bf[4][4];
#pragma unroll
                for (int p = 0; p < 4; p++) {
                    uint32_t off = SMEM_SWIZZLE_128B((uint32_t)((n0w + p * 16 + brow) * 128 + ks * 32 + bbyt));
                    ldsm4(bf[p], sb + 16384 + off);
                }
#pragma unroll
                for (int mi = 0; mi < 4; mi++)
#pragma unroll
                    for (int ni = 0; ni < 8; ni++)
                        mma_fp16(c[mi][ni], af[mi], &bf[ni >> 1][(ni & 1) * 2]);
            }
            cur = (cur + 1) % GSTAGES;
        }

        // epilogue for this tile (registers -> gmem; overlaps in-flight loads)
#pragma unroll
        for (int mi = 0; mi < 4; mi++) {
            const int r0 = m0 + m0w + mi * 16 + (lane >> 2);
#pragma unroll
            for (int ni = 0; ni < 8; ni++) {
                const int cc = n0 + n0w + ni * 8 + (lane & 3) * 2;
                __half2 p0 = __floats2half2_rn(c[mi][ni][0], c[mi][ni][1]);
                __half2 p1 = __floats2half2_rn(c[mi][ni][2], c[mi][ni][3]);
                *(__half2*)(C + (size_t)r0 * ldC + cc)       = p0;
                *(__half2*)(C + (size_t)(r0 + 8) * ldC + cc) = p1;
            }
        }

        if (!has_next) break;
#pragma unroll
        for (int mi = 0; mi < 4; mi++)
#pragma unroll
            for (int ni = 0; ni < 8; ni++)
#pragma unroll
                for (int e = 0; e < 4; e++) c[mi][ni][e] = 0.0f;
        tile = next_tile; m0 = nm0; n0 = nn0;
    }
}

// ===================== HMMA attention: 2 heads per CTA (256 thr) ============
#define ATTN_SMEM (8 * 8192)     // Q,K,V,S x 2 heads x 8KB

__global__ __launch_bounds__(256) void attn_hmma() {
    extern __shared__ char asm_[];
    const int bh2  = blockIdx.x;       // 0..2047
    const int b    = bh2 >> 3;
    const int h0   = (bh2 & 7) * 2;
    const int tid  = threadIdx.x;
    const int lane = tid & 31;
    const int wid  = tid >> 5;
    const int wh   = wid >> 2;         // head select
    const int wl   = wid & 3;          // warp within head

    char* const s_p = asm_ + 49152 + wh * 8192;
    const uint32_t base_s = smem_to_u32(asm_);
    const uint32_t q_s = base_s + wh * 8192;
    const uint32_t k_s = base_s + 16384 + wh * 8192;
    const uint32_t v_s = base_s + 32768 + wh * 8192;
    const uint32_t s_s = base_s + 49152 + wh * 8192;

    const size_t qbase = (size_t)(b * KS) * NQKV + h0 * DHEAD;
#pragma unroll
    for (int i = 0; i < 4; i++) {
        int idx = tid + i * 256;           // 0..1023 chunks (64 rows x 16)
        int r = idx >> 4, c16 = idx & 15;
        int hd = c16 >> 3, ch = c16 & 7;
        size_t ga = qbase + (size_t)r * NQKV + c16 * 8;
        uint32_t so = hd * 8192 + SMEM_SWIZZLE_128B((uint32_t)(r * 128 + ch * 16));
        CP_ASYNC16(base_s + so,          &g_qkvh[ga]);
        CP_ASYNC16(base_s + 16384 + so,  &g_qkvh[ga + 1024]);
        CP_ASYNC16(base_s + 32768 + so,  &g_qkvh[ga + 2048]);
    }
    CP_COMMIT();
    CP_WAIT(0);
    __syncthreads();

    // ---- S = Q @ K^T ----
    float c[8][4];
#pragma unroll
    for (int nb = 0; nb < 8; nb++)
#pragma unroll
        for (int e = 0; e < 4; e++) c[nb][e] = 0.0f;

    const int arow = wl * 16 + (lane & 15);
    const int abyt = ((lane >> 4) & 1) * 16;
    const int brow = ((lane >> 4) & 1) * 8 + (lane & 7);
    const int bbyt = ((lane >> 3) & 1) * 16;

#pragma unroll
    for (int ks = 0; ks < 4; ks++) {
        uint32_t af[4];
        ldsm4(af, q_s + SMEM_SWIZZLE_128B((uint32_t)(arow * 128 + ks * 32 + abyt)));
        uint32_t bf[4][4];
#pragma unroll
        for (int p = 0; p < 4; p++)
            ldsm4(bf[p], k_s + SMEM_SWIZZLE_128B((uint32_t)((p * 16 + brow) * 128 + ks * 32 + bbyt)));
#pragma unroll
        for (int nb = 0; nb < 8; nb++)
            mma_fp16(c[nb], af, &bf[nb >> 1][(nb & 1) * 2]);
    }

    // ---- softmax + mask ----
    const int r0 = wl * 16 + (lane >> 2);
    const int r1 = r0 + 8;
    float m0 = -1e30f, m1 = -1e30f;
#pragma unroll
    for (int nb = 0; nb < 8; nb++) {
#pragma unroll
        for (int e = 0; e < 4; e++) c[nb][e] *= SCALE;
        m0 = fmaxf(m0, fmaxf(c[nb][0], c[nb][1]));
        m1 = fmaxf(m1, fmaxf(c[nb][2], c[nb][3]));
    }
    m0 = fmaxf(m0, __shfl_xor_sync(0xffffffffu, m0, 1));
    m0 = fmaxf(m0, __shfl_xor_sync(0xffffffffu, m0, 2));
    m1 = fmaxf(m1, __shfl_xor_sync(0xffffffffu, m1, 1));
    m1 = fmaxf(m1, __shfl_xor_sync(0xffffffffu, m1, 2));
    float s0 = 0.0f, s1 = 0.0f;
#pragma unroll
    for (int nb = 0; nb < 8; nb++) {
        c[nb][0] = __expf(c[nb][0] - m0); s0 += c[nb][0];
        c[nb][1] = __expf(c[nb][1] - m0); s0 += c[nb][1];
        c[nb][2] = __expf(c[nb][2] - m1); s1 += c[nb][2];
        c[nb][3] = __expf(c[nb][3] - m1); s1 += c[nb][3];
    }
    s0 += __shfl_xor_sync(0xffffffffu, s0, 1);
    s0 += __shfl_xor_sync(0xffffffffu, s0, 2);
    s1 += __shfl_xor_sync(0xffffffffu, s1, 1);
    s1 += __shfl_xor_sync(0xffffffffu, s1, 2);
    const float w0 = g_mask[b * KS + r0] / s0;
    const float w1 = g_mask[b * KS + r1] / s1;

    const int scol = (lane & 3) * 2;
#pragma unroll
    for (int nb = 0; nb < 8; nb++) {
        __half2 p0 = __floats2half2_rn(c[nb][0] * w0, c[nb][1] * w0);
        __half2 p1 = __floats2half2_rn(c[nb][2] * w1, c[nb][3] * w1);
        *(__half2*)(s_p + SMEM_SWIZZLE_128B((uint32_t)(r0 * 128 + (nb * 8 + scol) * 2))) = p0;
        *(__half2*)(s_p + SMEM_SWIZZLE_128B((uint32_t)(r1 * 128 + (nb * 8 + scol) * 2))) = p1;
    }
    __syncwarp();

    // ---- O = S @ V ----
    float o[8][4];
#pragma unroll
    for (int nb = 0; nb < 8; nb++)
#pragma unroll
        for (int e = 0; e < 4; e++) o[nb][e] = 0.0f;

    const int g  = lane >> 3;
    const int gr = lane & 7;
#pragma unroll
    for (int ks = 0; ks < 4; ks++) {
        uint32_t af[4];
        ldsm4(af, s_s + SMEM_SWIZZLE_128B((uint32_t)(arow * 128 + ks * 32 + abyt)));
#pragma unroll
        for (int np = 0; np < 4; np++) {
            uint32_t bf[4];
            const int krow = ks * 16 + (g & 1) * 8 + gr;
            const int dcol = np * 16 + (g >> 1) * 8;
            ldsm4t(bf, v_s + SMEM_SWIZZLE_128B((uint32_t)(krow * 128 + dcol * 2)));
            mma_fp16(o[np * 2 + 0], af, &bf[0]);
            mma_fp16(o[np * 2 + 1], af, &bf[2]);
        }
    }

    const int h = h0 + wh;
    const size_t obase = (size_t)(b * KS) * DMODEL + h * DHEAD;
#pragma unroll
    for (int nb = 0; nb < 8; nb++) {
        __half2 p0 = __floats2half2_rn(o[nb][0], o[nb][1]);
        __half2 p1 = __floats2half2_rn(o[nb][2], o[nb][3]);
        *(__half2*)&g_aoh[obase + (size_t)r0 * DMODEL + nb * 8 + scol] = p0;
        *(__half2*)&g_aoh[obase + (size_t)r1 * DMODEL + nb * 8 + scol] = p1;
    }
}

// ===================== gated residual + LayerNorm ============
__global__ __launch_bounds__(256) void resid_ln(
    const float* __restrict__ hidden, const float* __restrict__ gamma,
    const float* __restrict__ beta, float* __restrict__ out)
{
    __shared__ float red[2][8];
    const int r = blockIdx.x;
    const float m = g_mask[r];
    const int c = threadIdx.x * 4;
    const size_t base = (size_t)r * DMODEL;

    float4 hv = *(const float4*)(hidden + base + c);
    uint2 pu = *(const uint2*)(&g_projh[base + c]);
    __half2 ph0 = *(__half2*)&pu.x;
    __half2 ph1 = *(__half2*)&pu.y;
    float2 pf0 = __half22float2(ph0);
    float2 pf1 = __half22float2(ph1);
    float v[4] = {hv.x + m * pf0.x, hv.y + m * pf0.y,
                  hv.z + m * pf1.x, hv.w + m * pf1.y};

    float s  = v[0] + v[1] + v[2] + v[3];
    float sq = v[0]*v[0] + v[1]*v[1] + v[2]*v[2] + v[3]*v[3];
#pragma unroll
    for (int o = 16; o; o >>= 1) {
        s  += __shfl_xor_sync(0xffffffffu, s, o);
        sq += __shfl_xor_sync(0xffffffffu, sq, o);
    }
    const int wid = threadIdx.x >> 5, lid = threadIdx.x & 31;
    if (lid == 0) { red[0][wid] = s; red[1][wid] = sq; }
    __syncthreads();
    s = 0.0f; sq = 0.0f;
#pragma unroll
    for (int i = 0; i < 8; i++) { s += red[0][i]; sq += red[1][i]; }

    const float mu  = s  * (1.0f / DMODEL);
    const float var = sq * (1.0f / DMODEL) - mu * mu;
    const float inv = rsqrtf(var + LNEPS);

    float4 g4 = *(const float4*)(gamma + c);
    float4 b4 = *(const float4*)(beta + c);
    float4 o4;
    o4.x = (v[0] - mu) * inv * g4.x + b4.x;
    o4.y = (v[1] - mu) * inv * g4.y + b4.y;
    o4.z = (v[2] - mu) * inv * g4.z + b4.z;
    o4.w = (v[3] - mu) * inv * g4.w + b4.w;
    *(float4*)(out + base + c) = o4;
}

// ===================== launch =====================
extern "C" void kernel_launch(void* const* d_in, const int* in_sizes, int n_in,
                              void* d_out, int out_size)
{
    const float* hidden = (const float*)d_in[0];
    const void*  mask   = d_in[1];
    const float* W[4]   = {(const float*)d_in[2], (const float*)d_in[3],
                           (const float*)d_in[4], (const float*)d_in[5]};
    const float* gamma  = (const float*)d_in[6];
    const float* beta   = (const float*)d_in[7];
    float* out = (float*)d_out;

    __half *phh, *pqkvh, *paoh, *pprojh, *pwh;
    cudaGetSymbolAddress((void**)&phh,    g_hh);
    cudaGetSymbolAddress((void**)&pqkvh,  g_qkvh);
    cudaGetSymbolAddress((void**)&paoh,   g_aoh);
    cudaGetSymbolAddress((void**)&pprojh, g_projh);
    cudaGetSymbolAddress((void**)&pwh,    g_wh);

    cudaFuncSetAttribute(gemm_fp16, cudaFuncAttributeMaxDynamicSharedMemorySize, GEMM_SMEM);
    cudaFuncSetAttribute(attn_hmma, cudaFuncAttributeMaxDynamicSharedMemorySize, ATTN_SMEM);

    detect_mask<<<1, 256>>>((const unsigned char*)mask);
    norm_mask<<<NROWS / 256, 256>>>(mask);

    conv_all<<<20480, 256>>>((const float4*)hidden,
        (const float4*)W[0], (const float4*)W[1], (const float4*)W[2], (const float4*)W[3],
        (uint2*)phh, (uint2*)pwh);

    gemm_fp16<<<GEMM_GRID, 128, GEMM_SMEM>>>(phh, pwh, pqkvh, NQKV);

    attn_hmma<<<NB * NH / 2, 256, ATTN_SMEM>>>();

    gemm_fp16<<<GEMM_GRID, 128, GEMM_SMEM>>>(paoh, pwh + 3 * (size_t)DMODEL * DMODEL, pprojh, DMODEL);

    resid_ln<<<NROWS, 256>>>(hidden, gamma, beta, out);
}